// round 2
// baseline (speedup 1.0000x reference)
#include <cuda_runtime.h>
#include <math.h>
#include <float.h>

// Problem constants
#define BB  8
#define SS  1024
#define EE  512
#define HH  8
#define DD  64
#define FFD 2048
#define LLAYERS 4
#define MTOT (BB*SS)   // 8192 rows

// ---------------- scratch (static device globals; no allocations) -----------
__device__ float g_x   [BB*SS*EE];        // running residual stream (16MB)
__device__ float g_h   [BB*SS*EE];        // layernorm output
__device__ float g_q   [BB*SS*EE];
__device__ float g_k   [BB*SS*EE];
__device__ float g_v   [BB*SS*EE];
__device__ float g_attn[BB*SS*EE];
__device__ float g_ffn [BB*SS*FFD];                   // 64MB
__device__ float g_sc  [(size_t)BB*HH*SS*SS];         // 256MB scores

// ---------------- generic tiled SGEMM -----------------------------------
// C[M,N] = epilogue( sum_k A[m,k]*B[k,n] )  batched via blockIdx.z
// EPI: 0 = +bias, 1 = gelu(+bias), 2 = +bias+residual, 3 = scores(scale,mask,edge)
template<int EPI, bool TB>
__global__ __launch_bounds__(256)
void gemm_k(const float* __restrict__ A, int lda, long long sA0, long long sA1,
            const float* __restrict__ Bg, int ldb, long long sB0, long long sB1,
            float* __restrict__ C, int ldc, long long sC0, long long sC1,
            const float* __restrict__ bias,
            const float* __restrict__ res,
            int M, int N, int K, float alpha, int batchH,
            const float* __restrict__ edge,
            const unsigned char* __restrict__ mask)
{
    __shared__ float As[16][128];
    __shared__ float Bs[16][64];

    const int z  = blockIdx.z;
    const int zb = z / batchH;
    const int zh = z - zb * batchH;
    A  += (size_t)zb * sA0 + (size_t)zh * sA1;
    Bg += (size_t)zb * sB0 + (size_t)zh * sB1;
    C  += (size_t)zb * sC0 + (size_t)zh * sC1;

    const int tid = threadIdx.x;
    const int tx  = tid & 15;          // 16 col-groups * 4 cols
    const int ty  = tid >> 4;          // 16 row-groups * 8 rows
    const int m0  = blockIdx.y * 128;
    const int n0  = blockIdx.x * 64;

    float acc[8][4];
#pragma unroll
    for (int i = 0; i < 8; i++)
#pragma unroll
        for (int j = 0; j < 4; j++) acc[i][j] = 0.f;

    const int nkt = K >> 4;
    for (int kt = 0; kt < nkt; ++kt) {
        const int k0 = kt << 4;
        // load A tile 128x16 (coalesced), store transposed As[k][m]
#pragma unroll
        for (int i = 0; i < 2; i++) {
            int idx = i * 256 + tid;
            int row = idx >> 2, kq = idx & 3;
            float4 av = *(const float4*)(A + (size_t)(m0 + row) * lda + k0 + kq * 4);
            As[kq*4+0][row] = av.x; As[kq*4+1][row] = av.y;
            As[kq*4+2][row] = av.z; As[kq*4+3][row] = av.w;
        }
        // load B tile 16x64
        if (!TB) {
            int r = tid >> 4, cq = tid & 15;
            float4 bv = *(const float4*)(Bg + (size_t)(k0 + r) * ldb + n0 + cq * 4);
            *(float4*)&Bs[r][cq*4] = bv;
        } else {
            int n = tid >> 2, kq = tid & 3;
            float4 bv = *(const float4*)(Bg + (size_t)(n0 + n) * ldb + k0 + kq * 4);
            Bs[kq*4+0][n] = bv.x; Bs[kq*4+1][n] = bv.y;
            Bs[kq*4+2][n] = bv.z; Bs[kq*4+3][n] = bv.w;
        }
        __syncthreads();
#pragma unroll
        for (int k = 0; k < 16; k++) {
            float4 a0 = *(const float4*)&As[k][ty*8];
            float4 a1 = *(const float4*)&As[k][ty*8+4];
            float4 b4 = *(const float4*)&Bs[k][tx*4];
            float ar[8] = {a0.x,a0.y,a0.z,a0.w,a1.x,a1.y,a1.z,a1.w};
            float br[4] = {b4.x,b4.y,b4.z,b4.w};
#pragma unroll
            for (int i = 0; i < 8; i++)
#pragma unroll
                for (int j = 0; j < 4; j++)
                    acc[i][j] = fmaf(ar[i], br[j], acc[i][j]);
        }
        __syncthreads();
    }

    // epilogue
#pragma unroll
    for (int j = 0; j < 4; j++) {
        const int c = n0 + tx * 4 + j;
        float bv = 0.f;
        if (EPI != 3 && bias) bv = __ldg(bias + c);
        bool padc = false;
        if (EPI == 3) padc = (mask[(size_t)zb * N + c] != 0);
#pragma unroll
        for (int i = 0; i < 8; i++) {
            const int r = m0 + ty * 8 + i;
            float v = acc[i][j];
            if (EPI == 0) {
                v += bv;
            } else if (EPI == 1) {
                v += bv;
                v = 0.5f * v * (1.f + erff(v * 0.70710678118654752f));
            } else if (EPI == 2) {
                v += bv + res[(size_t)r * ldc + c];
            } else { // scores
                v = padc ? -FLT_MAX : v * alpha;
                v += edge[(size_t)zb * M * N + (size_t)r * N + c];
            }
            C[(size_t)r * ldc + c] = v;
        }
    }
}

// ---------------- layernorm: one block (128 thr) per row of 512 ------------
__global__ __launch_bounds__(128)
void ln_k(const float* __restrict__ x, const float* __restrict__ g,
          const float* __restrict__ b, float* __restrict__ o)
{
    const size_t row = blockIdx.x;
    const int tid = threadIdx.x;
    __shared__ float sma[4], smb[4];

    float4 v = ((const float4*)(x + row * EE))[tid];
    float s = v.x + v.y + v.z + v.w;
#pragma unroll
    for (int off = 16; off > 0; off >>= 1) s += __shfl_xor_sync(0xffffffffu, s, off);
    if ((tid & 31) == 0) sma[tid >> 5] = s;
    __syncthreads();
    const float mu = (sma[0] + sma[1] + sma[2] + sma[3]) * (1.f / EE);

    float4 d = make_float4(v.x - mu, v.y - mu, v.z - mu, v.w - mu);
    float s2 = d.x*d.x + d.y*d.y + d.z*d.z + d.w*d.w;
#pragma unroll
    for (int off = 16; off > 0; off >>= 1) s2 += __shfl_xor_sync(0xffffffffu, s2, off);
    if ((tid & 31) == 0) smb[tid >> 5] = s2;
    __syncthreads();
    const float var = (smb[0] + smb[1] + smb[2] + smb[3]) * (1.f / EE);
    const float rstd = rsqrtf(var + 1e-5f);

    float4 gg = ((const float4*)g)[tid];
    float4 bb = ((const float4*)b)[tid];
    float4 out = make_float4(d.x*rstd*gg.x + bb.x, d.y*rstd*gg.y + bb.y,
                             d.z*rstd*gg.z + bb.z, d.w*rstd*gg.w + bb.w);
    ((float4*)(o + row * EE))[tid] = out;
}

// ---------------- softmax: one block (256 thr) per row of 1024 --------------
__global__ __launch_bounds__(256)
void softmax_k(float* __restrict__ s)
{
    float* p = s + (size_t)blockIdx.x * SS;
    const int tid = threadIdx.x;
    __shared__ float sma[8], smb[8];

    float4 v = ((float4*)p)[tid];
    float m = fmaxf(fmaxf(v.x, v.y), fmaxf(v.z, v.w));
#pragma unroll
    for (int off = 16; off > 0; off >>= 1) m = fmaxf(m, __shfl_xor_sync(0xffffffffu, m, off));
    if ((tid & 31) == 0) sma[tid >> 5] = m;
    __syncthreads();
    m = sma[0];
#pragma unroll
    for (int i = 1; i < 8; i++) m = fmaxf(m, sma[i]);

    v.x = expf(v.x - m); v.y = expf(v.y - m);
    v.z = expf(v.z - m); v.w = expf(v.w - m);
    float su = v.x + v.y + v.z + v.w;
#pragma unroll
    for (int off = 16; off > 0; off >>= 1) su += __shfl_xor_sync(0xffffffffu, su, off);
    if ((tid & 31) == 0) smb[tid >> 5] = su;
    __syncthreads();
    float tot = smb[0];
#pragma unroll
    for (int i = 1; i < 8; i++) tot += smb[i];
    const float inv = 1.f / tot;
    v.x *= inv; v.y *= inv; v.z *= inv; v.w *= inv;
    ((float4*)p)[tid] = v;
}

// ---------------- host orchestration ---------------------------------------
extern "C" void kernel_launch(void* const* d_in, const int* in_sizes, int n_in,
                              void* d_out, int out_size)
{
    const float* src  = (const float*)d_in[0];
    const float* edge = (const float*)d_in[1];
    const unsigned char* mask = (const unsigned char*)d_in[2];
    const float* Wq = (const float*)d_in[3];
    const float* bq = (const float*)d_in[4];
    const float* Wk = (const float*)d_in[5];
    const float* bk = (const float*)d_in[6];
    const float* Wv = (const float*)d_in[7];
    const float* bv = (const float*)d_in[8];
    const float* Wo = (const float*)d_in[9];
    const float* bo = (const float*)d_in[10];
    const float* ln1g = (const float*)d_in[11];
    const float* ln1b = (const float*)d_in[12];
    const float* ln2g = (const float*)d_in[13];
    const float* ln2b = (const float*)d_in[14];
    const float* W1 = (const float*)d_in[15];
    const float* b1 = (const float*)d_in[16];
    const float* W2 = (const float*)d_in[17];
    const float* b2 = (const float*)d_in[18];

    float *x, *h, *q, *kk, *vv, *attn, *sc, *ffn;
    cudaGetSymbolAddress((void**)&x,    g_x);
    cudaGetSymbolAddress((void**)&h,    g_h);
    cudaGetSymbolAddress((void**)&q,    g_q);
    cudaGetSymbolAddress((void**)&kk,   g_k);
    cudaGetSymbolAddress((void**)&vv,   g_v);
    cudaGetSymbolAddress((void**)&attn, g_attn);
    cudaGetSymbolAddress((void**)&sc,   g_sc);
    cudaGetSymbolAddress((void**)&ffn,  g_ffn);

    cudaMemcpyAsync(x, src, sizeof(float) * (size_t)MTOT * EE,
                    cudaMemcpyDeviceToDevice);

    const long long sQ0 = (long long)SS * EE;   // per-batch stride in q/k/v/attn
    const long long sQ1 = DD;                   // per-head stride
    const long long sS0 = (long long)HH * SS * SS;
    const long long sS1 = (long long)SS * SS;

    for (int l = 0; l < LLAYERS; ++l) {
        const float* wq = Wq + (size_t)l * EE * EE;
        const float* wk = Wk + (size_t)l * EE * EE;
        const float* wv = Wv + (size_t)l * EE * EE;
        const float* wo = Wo + (size_t)l * EE * EE;
        const float* w1 = W1 + (size_t)l * EE * FFD;
        const float* w2 = W2 + (size_t)l * FFD * EE;

        // LN1
        ln_k<<<MTOT, 128>>>(x, ln1g + l * EE, ln1b + l * EE, h);

        // Q, K, V projections: [8192x512] @ [512x512]
        dim3 gP(EE / 64, MTOT / 128, 1);
        gemm_k<0,false><<<gP,256>>>(h, EE,0,0, wq, EE,0,0, q,  EE,0,0,
                                    bq + l*EE, nullptr, MTOT, EE, EE, 1.f, 1, nullptr, nullptr);
        gemm_k<0,false><<<gP,256>>>(h, EE,0,0, wk, EE,0,0, kk, EE,0,0,
                                    bk + l*EE, nullptr, MTOT, EE, EE, 1.f, 1, nullptr, nullptr);
        gemm_k<0,false><<<gP,256>>>(h, EE,0,0, wv, EE,0,0, vv, EE,0,0,
                                    bv + l*EE, nullptr, MTOT, EE, EE, 1.f, 1, nullptr, nullptr);

        // scores = scale*Q@K^T, mask, +edge_bias  (batched over B*H)
        dim3 gS(SS / 64, SS / 128, BB * HH);
        gemm_k<3,true><<<gS,256>>>(q, EE, sQ0, sQ1, kk, EE, sQ0, sQ1,
                                   sc, SS, sS0, sS1,
                                   nullptr, nullptr, SS, SS, DD, 0.125f, HH,
                                   edge, mask);

        // softmax over last dim
        softmax_k<<<BB * HH * SS, 256>>>(sc);

        // attn = probs @ V  (batched, N=64)
        dim3 gA(1, SS / 128, BB * HH);
        gemm_k<0,false><<<gA,256>>>(sc, SS, sS0, sS1, vv, EE, sQ0, sQ1,
                                    attn, EE, sQ0, sQ1,
                                    nullptr, nullptr, SS, DD, SS, 1.f, HH,
                                    nullptr, nullptr);

        // x = x + attn @ Wo + bo  (in-place residual)
        gemm_k<2,false><<<gP,256>>>(attn, EE,0,0, wo, EE,0,0, x, EE,0,0,
                                    bo + l*EE, x, MTOT, EE, EE, 1.f, 1, nullptr, nullptr);

        // LN2
        ln_k<<<MTOT, 128>>>(x, ln2g + l * EE, ln2b + l * EE, h);

        // FFN1 with exact GELU: [8192x512] @ [512x2048]
        dim3 gF1(FFD / 64, MTOT / 128, 1);
        gemm_k<1,false><<<gF1,256>>>(h, EE,0,0, w1, FFD,0,0, ffn, FFD,0,0,
                                     b1 + l*FFD, nullptr, MTOT, FFD, EE, 1.f, 1, nullptr, nullptr);

        // FFN2 + residual: [8192x2048] @ [2048x512]
        gemm_k<2,false><<<gP,256>>>(ffn, FFD,0,0, w2, EE,0,0, x, EE,0,0,
                                    b2 + l*EE, x, MTOT, EE, FFD, 1.f, 1, nullptr, nullptr);
    }

    cudaMemcpyAsync(d_out, x, sizeof(float) * (size_t)MTOT * EE,
                    cudaMemcpyDeviceToDevice);
}

// round 4
// speedup vs baseline: 2.7360x; 2.7360x over previous
#include <cuda_runtime.h>
#include <cstdint>
#include <math.h>
#include <float.h>

// Problem constants
#define BB  8
#define SS  1024
#define EE  512
#define HH  8
#define DD  64
#define FFD 2048
#define LLAYERS 4
#define MTOT (BB*SS)   // 8192 rows

// ---------------- scratch (static device globals; no allocations) -----------
__device__ float g_x   [BB*SS*EE];
__device__ float g_h   [BB*SS*EE];
__device__ float g_q   [BB*SS*EE];
__device__ float g_k   [BB*SS*EE];
__device__ float g_v   [BB*SS*EE];
__device__ float g_vT  [BB*HH*DD*SS];
__device__ float g_attn[BB*SS*EE];
__device__ float g_ffn [BB*SS*FFD];
__device__ float g_sc  [(size_t)BB*HH*SS*SS];        // 256MB scores
// transposed weights (B operand is [N,K] row-major = K-major)
__device__ float g_wqT[LLAYERS*EE*EE];
__device__ float g_wkT[LLAYERS*EE*EE];
__device__ float g_wvT[LLAYERS*EE*EE];
__device__ float g_woT[LLAYERS*EE*EE];
__device__ float g_w1T[LLAYERS*FFD*EE];
__device__ float g_w2T[LLAYERS*EE*FFD];

// ---------------- helpers ---------------------------------------------------
__device__ __forceinline__ uint32_t smem_u32(const void* p) {
    uint32_t a;
    asm("{ .reg .u64 t; cvta.to.shared.u64 t, %1; cvt.u32.u64 %0, t; }" : "=r"(a) : "l"(p));
    return a;
}
__device__ __forceinline__ float to_tf32(float x) {
    float r; asm("cvt.rna.tf32.f32 %0, %1;" : "=f"(r) : "f"(x)); return r;
}
#define CP_ASYNC16(dst, src) \
    asm volatile("cp.async.ca.shared.global [%0], [%1], 16;" :: "r"(dst), "l"(src))
#define CP_COMMIT() asm volatile("cp.async.commit_group;" ::: "memory")
#define CP_WAIT1()  asm volatile("cp.async.wait_group 1;" ::: "memory")
#define CP_WAIT0()  asm volatile("cp.async.wait_group 0;" ::: "memory")

// ---------------- mma.sync tf32 GEMM ----------------------------------------
// C[M,N] = epi( A[M,K] @ B[N,K]^T ).  BM=128, BN template, BK=32.
// 256 threads = 8 warps, warp grid 4x2, warp tile 32 x (BN/2).
// EPI: 0 +bias, 1 gelu(+bias), 2 +bias+res, 3 scores(scale,mask,edge)
template<int EPI, int BN>
__global__ void __launch_bounds__(256)
mma_gemm(const float* __restrict__ A, int lda, long long sAb, long long sAh,
         const float* __restrict__ Bm, int ldb, long long sBb, long long sBh,
         float* __restrict__ C, int ldc, long long sCb, long long sCh,
         const float* __restrict__ bias, const float* __restrict__ res,
         int M, int N, int K, float alpha, int batchH,
         const float* __restrict__ edge, const unsigned char* __restrict__ mask)
{
    constexpr int BM = 128, PAD = 36;
    constexpr int WN = BN / 2, NI = WN / 8;

    extern __shared__ float sm[];
    float* Asm = sm;                       // [2][BM*PAD]
    float* Bsm = sm + 2 * BM * PAD;        // [2][BN*PAD]
    const uint32_t sbA = smem_u32(Asm), sbB = smem_u32(Bsm);

    const int z = blockIdx.z, zb = z / batchH, zh = z - zb * batchH;
    A  += (size_t)zb * sAb + (size_t)zh * sAh;
    Bm += (size_t)zb * sBb + (size_t)zh * sBh;
    C  += (size_t)zb * sCb + (size_t)zh * sCh;
    const float* resp = res ? res + (size_t)zb * sCb + (size_t)zh * sCh : nullptr;

    const int tid = threadIdx.x, warp = tid >> 5, lane = tid & 31;
    const int g = lane >> 2, tg = lane & 3;
    const int wr = warp & 3, wc = warp >> 2;

    const int m0 = blockIdx.y * BM, n0 = blockIdx.x * BN;

    float acc[2][NI][4];
#pragma unroll
    for (int mi = 0; mi < 2; mi++)
#pragma unroll
        for (int ni = 0; ni < NI; ni++)
#pragma unroll
            for (int j = 0; j < 4; j++) acc[mi][ni][j] = 0.f;

    auto load_chunk = [&](int c, int buf) {
        const float* Ab = A + (size_t)m0 * lda + c * 32;
#pragma unroll
        for (int i = 0; i < 4; i++) {
            int e = i * 256 + tid, row = e >> 3, c4 = e & 7;
            CP_ASYNC16(sbA + (uint32_t)(((buf * BM + row) * PAD + c4 * 4) * 4),
                       Ab + (size_t)row * lda + c4 * 4);
        }
        const float* Bb = Bm + (size_t)n0 * ldb + c * 32;
#pragma unroll
        for (int i = 0; i < BN / 32; i++) {
            int e = i * 256 + tid, row = e >> 3, c4 = e & 7;
            CP_ASYNC16(sbB + (uint32_t)(((buf * BN + row) * PAD + c4 * 4) * 4),
                       Bb + (size_t)row * ldb + c4 * 4);
        }
        CP_COMMIT();
    };

    auto compute = [&](int buf) {
        const float* Ab = Asm + buf * BM * PAD;
        const float* Bb = Bsm + buf * BN * PAD;
#pragma unroll
        for (int ks = 0; ks < 4; ks++) {
            const int k0 = ks * 8;
            uint32_t af[2][4];
#pragma unroll
            for (int mi = 0; mi < 2; mi++) {
                const int rb = wr * 32 + mi * 16;
                af[mi][0] = __float_as_uint(to_tf32(Ab[(rb + g)     * PAD + k0 + tg]));
                af[mi][1] = __float_as_uint(to_tf32(Ab[(rb + g + 8) * PAD + k0 + tg]));
                af[mi][2] = __float_as_uint(to_tf32(Ab[(rb + g)     * PAD + k0 + tg + 4]));
                af[mi][3] = __float_as_uint(to_tf32(Ab[(rb + g + 8) * PAD + k0 + tg + 4]));
            }
            uint32_t bf[NI][2];
#pragma unroll
            for (int ni = 0; ni < NI; ni++) {
                const int nb = wc * WN + ni * 8;
                bf[ni][0] = __float_as_uint(to_tf32(Bb[(nb + g) * PAD + k0 + tg]));
                bf[ni][1] = __float_as_uint(to_tf32(Bb[(nb + g) * PAD + k0 + tg + 4]));
            }
#pragma unroll
            for (int mi = 0; mi < 2; mi++)
#pragma unroll
                for (int ni = 0; ni < NI; ni++)
                    asm volatile(
                        "mma.sync.aligned.m16n8k8.row.col.f32.tf32.tf32.f32 "
                        "{%0,%1,%2,%3}, {%4,%5,%6,%7}, {%8,%9}, {%0,%1,%2,%3};"
                        : "+f"(acc[mi][ni][0]), "+f"(acc[mi][ni][1]),
                          "+f"(acc[mi][ni][2]), "+f"(acc[mi][ni][3])
                        : "r"(af[mi][0]), "r"(af[mi][1]), "r"(af[mi][2]), "r"(af[mi][3]),
                          "r"(bf[ni][0]), "r"(bf[ni][1]));
        }
    };

    const int nch = K >> 5;
    load_chunk(0, 0);
    for (int c = 0; c < nch; ++c) {
        if (c + 1 < nch) { load_chunk(c + 1, (c + 1) & 1); CP_WAIT1(); }
        else             { CP_WAIT0(); }
        __syncthreads();
        compute(c & 1);
        __syncthreads();
    }

    // ---- epilogue ----
#pragma unroll
    for (int mi = 0; mi < 2; mi++)
#pragma unroll
        for (int ni = 0; ni < NI; ni++)
#pragma unroll
            for (int hh = 0; hh < 2; hh++) {
                const int r   = m0 + wr * 32 + mi * 16 + g + hh * 8;
                const int col = n0 + wc * WN + ni * 8 + tg * 2;
                float vx = acc[mi][ni][hh * 2], vy = acc[mi][ni][hh * 2 + 1];
                if (EPI <= 2 && bias) {
                    float2 bb = *(const float2*)(bias + col);
                    vx += bb.x; vy += bb.y;
                }
                if (EPI == 1) {
                    vx = 0.5f * vx * (1.f + erff(vx * 0.70710678118654752f));
                    vy = 0.5f * vy * (1.f + erff(vy * 0.70710678118654752f));
                }
                if (EPI == 2) {
                    float2 rr = *(const float2*)(resp + (size_t)r * ldc + col);
                    vx += rr.x; vy += rr.y;
                }
                if (EPI == 3) {
                    const unsigned char* Mp = mask + (size_t)zb * N + col;
                    float2 ee = *(const float2*)(edge + ((size_t)zb * M + r) * N + col);
                    vx = (Mp[0] ? -FLT_MAX : vx * alpha) + ee.x;
                    vy = (Mp[1] ? -FLT_MAX : vy * alpha) + ee.y;
                }
                *(float2*)(C + (size_t)r * ldc + col) = make_float2(vx, vy);
            }
}

// ---------------- transposes ------------------------------------------------
__global__ void transpose_s(const float* __restrict__ in, float* __restrict__ out,
                            int R, int Ccols)
{
    const size_t zo = (size_t)blockIdx.z * R * Ccols;
    in += zo; out += zo;
    __shared__ float t[32][33];
    const int c0 = blockIdx.x * 32, r0 = blockIdx.y * 32;
    const int x = threadIdx.x, y = threadIdx.y;
#pragma unroll
    for (int i = 0; i < 32; i += 8) t[y + i][x] = in[(size_t)(r0 + y + i) * Ccols + c0 + x];
    __syncthreads();
#pragma unroll
    for (int i = 0; i < 32; i += 8) out[(size_t)(c0 + y + i) * R + r0 + x] = t[x][y + i];
}

__global__ void vtrans_k(const float* __restrict__ v, float* __restrict__ vT)
{
    const int z = blockIdx.z, b = z >> 3, h = z & 7;
    const float* in = v + (size_t)b * SS * EE + h * DD;
    float* out = vT + (size_t)z * DD * SS;
    __shared__ float t[32][33];
    const int d0 = blockIdx.x * 32, s0 = blockIdx.y * 32;
    const int x = threadIdx.x, y = threadIdx.y;
#pragma unroll
    for (int i = 0; i < 32; i += 8) t[y + i][x] = in[(size_t)(s0 + y + i) * EE + d0 + x];
    __syncthreads();
#pragma unroll
    for (int i = 0; i < 32; i += 8) out[(size_t)(d0 + y + i) * SS + s0 + x] = t[x][y + i];
}

// ---------------- layernorm -------------------------------------------------
__global__ __launch_bounds__(128)
void ln_k(const float* __restrict__ x, const float* __restrict__ g,
          const float* __restrict__ b, float* __restrict__ o)
{
    const size_t row = blockIdx.x;
    const int tid = threadIdx.x;
    __shared__ float sma[4], smb[4];

    float4 v = ((const float4*)(x + row * EE))[tid];
    float s = v.x + v.y + v.z + v.w;
#pragma unroll
    for (int off = 16; off > 0; off >>= 1) s += __shfl_xor_sync(0xffffffffu, s, off);
    if ((tid & 31) == 0) sma[tid >> 5] = s;
    __syncthreads();
    const float mu = (sma[0] + sma[1] + sma[2] + sma[3]) * (1.f / EE);

    float4 d = make_float4(v.x - mu, v.y - mu, v.z - mu, v.w - mu);
    float s2 = d.x*d.x + d.y*d.y + d.z*d.z + d.w*d.w;
#pragma unroll
    for (int off = 16; off > 0; off >>= 1) s2 += __shfl_xor_sync(0xffffffffu, s2, off);
    if ((tid & 31) == 0) smb[tid >> 5] = s2;
    __syncthreads();
    const float var = (smb[0] + smb[1] + smb[2] + smb[3]) * (1.f / EE);
    const float rstd = rsqrtf(var + 1e-5f);

    float4 gg = ((const float4*)g)[tid];
    float4 bb = ((const float4*)b)[tid];
    float4 out = make_float4(d.x*rstd*gg.x + bb.x, d.y*rstd*gg.y + bb.y,
                             d.z*rstd*gg.z + bb.z, d.w*rstd*gg.w + bb.w);
    ((float4*)(o + row * EE))[tid] = out;
}

// ---------------- softmax ---------------------------------------------------
__global__ __launch_bounds__(256)
void softmax_k(float* __restrict__ s)
{
    float* p = s + (size_t)blockIdx.x * SS;
    const int tid = threadIdx.x;
    __shared__ float sma[8], smb[8];

    float4 v = ((float4*)p)[tid];
    float m = fmaxf(fmaxf(v.x, v.y), fmaxf(v.z, v.w));
#pragma unroll
    for (int off = 16; off > 0; off >>= 1) m = fmaxf(m, __shfl_xor_sync(0xffffffffu, m, off));
    if ((tid & 31) == 0) sma[tid >> 5] = m;
    __syncthreads();
    m = sma[0];
#pragma unroll
    for (int i = 1; i < 8; i++) m = fmaxf(m, sma[i]);

    v.x = expf(v.x - m); v.y = expf(v.y - m);
    v.z = expf(v.z - m); v.w = expf(v.w - m);
    float su = v.x + v.y + v.z + v.w;
#pragma unroll
    for (int off = 16; off > 0; off >>= 1) su += __shfl_xor_sync(0xffffffffu, su, off);
    if ((tid & 31) == 0) smb[tid >> 5] = su;
    __syncthreads();
    float tot = smb[0];
#pragma unroll
    for (int i = 1; i < 8; i++) tot += smb[i];
    const float inv = 1.f / tot;
    v.x *= inv; v.y *= inv; v.z *= inv; v.w *= inv;
    ((float4*)p)[tid] = v;
}

// ---------------- host orchestration ----------------------------------------
extern "C" void kernel_launch(void* const* d_in, const int* in_sizes, int n_in,
                              void* d_out, int out_size)
{
    const float* src  = (const float*)d_in[0];
    const float* edge = (const float*)d_in[1];
    const unsigned char* mask = (const unsigned char*)d_in[2];
    const float* Wq = (const float*)d_in[3];
    const float* bq = (const float*)d_in[4];
    const float* Wk = (const float*)d_in[5];
    const float* bk = (const float*)d_in[6];
    const float* Wv = (const float*)d_in[7];
    const float* bvv = (const float*)d_in[8];
    const float* Wo = (const float*)d_in[9];
    const float* bo = (const float*)d_in[10];
    const float* ln1g = (const float*)d_in[11];
    const float* ln1b = (const float*)d_in[12];
    const float* ln2g = (const float*)d_in[13];
    const float* ln2b = (const float*)d_in[14];
    const float* W1 = (const float*)d_in[15];
    const float* b1 = (const float*)d_in[16];
    const float* W2 = (const float*)d_in[17];
    const float* b2 = (const float*)d_in[18];

    float *x, *h, *q, *kk, *vv, *vT, *attn, *sc, *ffn;
    float *wqT, *wkT, *wvT, *woT, *w1T, *w2T;
    cudaGetSymbolAddress((void**)&x,    g_x);
    cudaGetSymbolAddress((void**)&h,    g_h);
    cudaGetSymbolAddress((void**)&q,    g_q);
    cudaGetSymbolAddress((void**)&kk,   g_k);
    cudaGetSymbolAddress((void**)&vv,   g_v);
    cudaGetSymbolAddress((void**)&vT,   g_vT);
    cudaGetSymbolAddress((void**)&attn, g_attn);
    cudaGetSymbolAddress((void**)&sc,   g_sc);
    cudaGetSymbolAddress((void**)&ffn,  g_ffn);
    cudaGetSymbolAddress((void**)&wqT,  g_wqT);
    cudaGetSymbolAddress((void**)&wkT,  g_wkT);
    cudaGetSymbolAddress((void**)&wvT,  g_wvT);
    cudaGetSymbolAddress((void**)&woT,  g_woT);
    cudaGetSymbolAddress((void**)&w1T,  g_w1T);
    cudaGetSymbolAddress((void**)&w2T,  g_w2T);

    // dynamic smem: (2*128*36 + 2*BN*36) * 4 bytes
    const int SM128 = (2 * 128 * 36 + 2 * 128 * 36) * 4;  // 73728
    const int SM64  = (2 * 128 * 36 + 2 * 64  * 36) * 4;  // 55296
    cudaFuncSetAttribute(mma_gemm<0,128>, cudaFuncAttributeMaxDynamicSharedMemorySize, SM128);
    cudaFuncSetAttribute(mma_gemm<1,128>, cudaFuncAttributeMaxDynamicSharedMemorySize, SM128);
    cudaFuncSetAttribute(mma_gemm<2,128>, cudaFuncAttributeMaxDynamicSharedMemorySize, SM128);
    cudaFuncSetAttribute(mma_gemm<3,128>, cudaFuncAttributeMaxDynamicSharedMemorySize, SM128);
    cudaFuncSetAttribute(mma_gemm<0,64>,  cudaFuncAttributeMaxDynamicSharedMemorySize, SM64);

    cudaMemcpyAsync(x, src, sizeof(float) * (size_t)MTOT * EE, cudaMemcpyDeviceToDevice);

    // Pre-transpose all weights (batched over layers)
    dim3 tb(32, 8);
    transpose_s<<<dim3(EE/32,  EE/32,  LLAYERS), tb>>>(Wq, wqT, EE, EE);
    transpose_s<<<dim3(EE/32,  EE/32,  LLAYERS), tb>>>(Wk, wkT, EE, EE);
    transpose_s<<<dim3(EE/32,  EE/32,  LLAYERS), tb>>>(Wv, wvT, EE, EE);
    transpose_s<<<dim3(EE/32,  EE/32,  LLAYERS), tb>>>(Wo, woT, EE, EE);
    transpose_s<<<dim3(FFD/32, EE/32,  LLAYERS), tb>>>(W1, w1T, EE, FFD);
    transpose_s<<<dim3(EE/32,  FFD/32, LLAYERS), tb>>>(W2, w2T, FFD, EE);

    const long long sQ0 = (long long)SS * EE;   // per-batch stride in q/k/v/attn
    const long long sQ1 = DD;                   // per-head stride
    const long long sS0 = (long long)HH * SS * SS;
    const long long sS1 = (long long)SS * SS;
    const long long sV0 = (long long)HH * DD * SS;
    const long long sV1 = (long long)DD * SS;

    for (int l = 0; l < LLAYERS; ++l) {
        const float* bwq = wqT + (size_t)l * EE * EE;
        const float* bwk = wkT + (size_t)l * EE * EE;
        const float* bwv = wvT + (size_t)l * EE * EE;
        const float* bwo = woT + (size_t)l * EE * EE;
        const float* bw1 = w1T + (size_t)l * FFD * EE;
        const float* bw2 = w2T + (size_t)l * EE * FFD;

        ln_k<<<MTOT, 128>>>(x, ln1g + l * EE, ln1b + l * EE, h);

        dim3 gP(EE / 128, MTOT / 128, 1);
        mma_gemm<0,128><<<gP, 256, SM128>>>(h, EE,0,0, bwq, EE,0,0, q,  EE,0,0,
            bq + l*EE, nullptr, MTOT, EE, EE, 1.f, 1, nullptr, nullptr);
        mma_gemm<0,128><<<gP, 256, SM128>>>(h, EE,0,0, bwk, EE,0,0, kk, EE,0,0,
            bk + l*EE, nullptr, MTOT, EE, EE, 1.f, 1, nullptr, nullptr);
        mma_gemm<0,128><<<gP, 256, SM128>>>(h, EE,0,0, bwv, EE,0,0, vv, EE,0,0,
            bvv + l*EE, nullptr, MTOT, EE, EE, 1.f, 1, nullptr, nullptr);

        vtrans_k<<<dim3(DD/32, SS/32, BB*HH), tb>>>(vv, vT);

        // scores = scale*Q@K^T (+mask, +edge)
        dim3 gS(SS / 128, SS / 128, BB * HH);
        mma_gemm<3,128><<<gS, 256, SM128>>>(q, EE, sQ0, sQ1, kk, EE, sQ0, sQ1,
            sc, SS, sS0, sS1, nullptr, nullptr, SS, SS, DD, 0.125f, HH, edge, mask);

        softmax_k<<<BB * HH * SS, 256>>>(sc);

        // attn = probs @ V
        dim3 gA(1, SS / 128, BB * HH);
        mma_gemm<0,64><<<gA, 256, SM64>>>(sc, SS, sS0, sS1, vT, SS, sV0, sV1,
            attn, EE, sQ0, sQ1, nullptr, nullptr, SS, DD, SS, 1.f, HH, nullptr, nullptr);

        // x = x + attn @ Wo + bo
        mma_gemm<2,128><<<gP, 256, SM128>>>(attn, EE,0,0, bwo, EE,0,0, x, EE,0,0,
            bo + l*EE, x, MTOT, EE, EE, 1.f, 1, nullptr, nullptr);

        ln_k<<<MTOT, 128>>>(x, ln2g + l * EE, ln2b + l * EE, h);

        // FFN1 + exact GELU
        dim3 gF(FFD / 128, MTOT / 128, 1);
        mma_gemm<1,128><<<gF, 256, SM128>>>(h, EE,0,0, bw1, EE,0,0, ffn, FFD,0,0,
            b1 + l*FFD, nullptr, MTOT, FFD, EE, 1.f, 1, nullptr, nullptr);

        // FFN2 + residual
        mma_gemm<2,128><<<gP, 256, SM128>>>(ffn, FFD,0,0, bw2, FFD,0,0, x, EE,0,0,
            b2 + l*EE, x, MTOT, EE, FFD, 1.f, 1, nullptr, nullptr);
    }

    cudaMemcpyAsync(d_out, x, sizeof(float) * (size_t)MTOT * EE, cudaMemcpyDeviceToDevice);
}

// round 5
// speedup vs baseline: 3.1506x; 1.1515x over previous
#include <cuda_runtime.h>
#include <cstdint>
#include <math.h>
#include <float.h>

// Problem constants
#define BB  8
#define SS  1024
#define EE  512
#define HH  8
#define DD  64
#define FFD 2048
#define LLAYERS 4
#define MTOT (BB*SS)   // 8192 rows

// ---------------- scratch (static device globals; no allocations) -----------
__device__ float g_x   [BB*SS*EE];
__device__ float g_h   [BB*SS*EE];
__device__ float g_q   [BB*SS*EE];
__device__ float g_k   [BB*SS*EE];
__device__ float g_v   [BB*SS*EE];
__device__ float g_vT  [BB*HH*DD*SS];
__device__ float g_attn[BB*SS*EE];
__device__ float g_ffn [BB*SS*FFD];
__device__ float g_sc  [(size_t)BB*HH*SS*SS];        // 256MB scores
// transposed weights (B operand is [N,K] row-major = K-major), tf32-pre-rounded
__device__ float g_wqT[LLAYERS*EE*EE];
__device__ float g_wkT[LLAYERS*EE*EE];
__device__ float g_wvT[LLAYERS*EE*EE];
__device__ float g_woT[LLAYERS*EE*EE];
__device__ float g_w1T[LLAYERS*FFD*EE];
__device__ float g_w2T[LLAYERS*EE*FFD];

// ---------------- helpers ---------------------------------------------------
__device__ __forceinline__ uint32_t smem_u32(const void* p) {
    uint32_t a;
    asm("{ .reg .u64 t; cvta.to.shared.u64 t, %1; cvt.u32.u64 %0, t; }" : "=r"(a) : "l"(p));
    return a;
}
__device__ __forceinline__ float to_tf32(float x) {
    float r; asm("cvt.rna.tf32.f32 %0, %1;" : "=f"(r) : "f"(x)); return r;
}
#define CP_ASYNC16(dst, src) \
    asm volatile("cp.async.ca.shared.global [%0], [%1], 16;" :: "r"(dst), "l"(src))
#define CP_COMMIT() asm volatile("cp.async.commit_group;" ::: "memory")
#define CP_WAIT1()  asm volatile("cp.async.wait_group 1;" ::: "memory")
#define CP_WAIT0()  asm volatile("cp.async.wait_group 0;" ::: "memory")
// tf32-as-b16 ldmatrix: thread lane receives float [lane>>2][lane&3] of each 8x4 tile
#define LDSM4(r0, r1, r2, r3, addr) \
    asm volatile("ldmatrix.sync.aligned.m8n8.x4.shared.b16 {%0,%1,%2,%3}, [%4];" \
        : "=r"(r0), "=r"(r1), "=r"(r2), "=r"(r3) : "r"(addr))

// ---------------- mma.sync tf32 GEMM ----------------------------------------
// C[M,N] = epi( A[M,K] @ B[N,K]^T ).  BM=128, BN template, BK=32.
// 256 threads = 8 warps, warp grid 4x2, warp tile 32 x (BN/2).
// All GEMM inputs are pre-rounded to tf32 by their producers -> no cvt inside.
// EPI: 0 +bias (round out), 1 gelu(+bias) (round out), 2 +bias+res, 3 scores
template<int EPI, int BN>
__global__ void __launch_bounds__(256)
mma_gemm(const float* __restrict__ A, int lda, long long sAb, long long sAh,
         const float* __restrict__ Bm, int ldb, long long sBb, long long sBh,
         float* __restrict__ C, int ldc, long long sCb, long long sCh,
         const float* __restrict__ bias, const float* __restrict__ res,
         int M, int N, int K, float alpha, int batchH,
         const float* __restrict__ edge, const unsigned char* __restrict__ mask)
{
    constexpr int BM = 128, PAD = 36;
    constexpr int WN = BN / 2, NI = WN / 8;
    constexpr bool RND = (EPI == 0 || EPI == 1);   // output feeds another GEMM

    extern __shared__ float sm[];
    float* Asm = sm;                       // [2][BM*PAD]
    float* Bsm = sm + 2 * BM * PAD;        // [2][BN*PAD]
    const uint32_t sbA = smem_u32(Asm), sbB = smem_u32(Bsm);

    const int z = blockIdx.z, zb = z / batchH, zh = z - zb * batchH;
    A  += (size_t)zb * sAb + (size_t)zh * sAh;
    Bm += (size_t)zb * sBb + (size_t)zh * sBh;
    C  += (size_t)zb * sCb + (size_t)zh * sCh;
    const float* resp = res ? res + (size_t)zb * sCb + (size_t)zh * sCh : nullptr;

    const int tid = threadIdx.x, warp = tid >> 5, lane = tid & 31;
    const int g = lane >> 2, tg = lane & 3;
    const int wr = warp & 3, wc = warp >> 2;

    const int m0 = blockIdx.y * BM, n0 = blockIdx.x * BN;

    // ldmatrix per-thread address components
    const int arow = wr * 32 + ((lane >> 3) & 1) * 8 + (lane & 7);
    const int acol = ((lane >> 4) & 1) * 4;
    const int brow = wc * WN + ((lane >> 4) & 1) * 8 + (lane & 7);
    const int bcol = ((lane >> 3) & 1) * 4;

    float acc[2][NI][4];
#pragma unroll
    for (int mi = 0; mi < 2; mi++)
#pragma unroll
        for (int ni = 0; ni < NI; ni++)
#pragma unroll
            for (int j = 0; j < 4; j++) acc[mi][ni][j] = 0.f;

    auto load_chunk = [&](int c, int buf) {
        const float* Ab = A + (size_t)m0 * lda + c * 32;
#pragma unroll
        for (int i = 0; i < 4; i++) {
            int e = i * 256 + tid, row = e >> 3, c4 = e & 7;
            CP_ASYNC16(sbA + (uint32_t)(((buf * BM + row) * PAD + c4 * 4) * 4),
                       Ab + (size_t)row * lda + c4 * 4);
        }
        const float* Bb = Bm + (size_t)n0 * ldb + c * 32;
#pragma unroll
        for (int i = 0; i < BN / 32; i++) {
            int e = i * 256 + tid, row = e >> 3, c4 = e & 7;
            CP_ASYNC16(sbB + (uint32_t)(((buf * BN + row) * PAD + c4 * 4) * 4),
                       Bb + (size_t)row * ldb + c4 * 4);
        }
        CP_COMMIT();
    };

    auto compute = [&](int buf) {
        const uint32_t baA = sbA + (uint32_t)(buf * BM * PAD * 4);
        const uint32_t baB = sbB + (uint32_t)(buf * BN * PAD * 4);
#pragma unroll
        for (int ks = 0; ks < 4; ks++) {
            const int k0 = ks * 8;
            uint32_t af[2][4];
#pragma unroll
            for (int mi = 0; mi < 2; mi++)
                LDSM4(af[mi][0], af[mi][1], af[mi][2], af[mi][3],
                      baA + (uint32_t)((((arow + mi * 16) * PAD) + k0 + acol) * 4));
            uint32_t bf[NI][2];
#pragma unroll
            for (int p = 0; p < NI / 2; p++) {
                uint32_t r0, r1, r2, r3;
                LDSM4(r0, r1, r2, r3,
                      baB + (uint32_t)((((brow + p * 16) * PAD) + k0 + bcol) * 4));
                bf[2*p][0] = r0; bf[2*p][1] = r1;
                bf[2*p+1][0] = r2; bf[2*p+1][1] = r3;
            }
#pragma unroll
            for (int mi = 0; mi < 2; mi++)
#pragma unroll
                for (int ni = 0; ni < NI; ni++)
                    asm volatile(
                        "mma.sync.aligned.m16n8k8.row.col.f32.tf32.tf32.f32 "
                        "{%0,%1,%2,%3}, {%4,%5,%6,%7}, {%8,%9}, {%0,%1,%2,%3};"
                        : "+f"(acc[mi][ni][0]), "+f"(acc[mi][ni][1]),
                          "+f"(acc[mi][ni][2]), "+f"(acc[mi][ni][3])
                        : "r"(af[mi][0]), "r"(af[mi][1]), "r"(af[mi][2]), "r"(af[mi][3]),
                          "r"(bf[ni][0]), "r"(bf[ni][1]));
        }
    };

    const int nch = K >> 5;
    load_chunk(0, 0);
    for (int c = 0; c < nch; ++c) {
        if (c + 1 < nch) { load_chunk(c + 1, (c + 1) & 1); CP_WAIT1(); }
        else             { CP_WAIT0(); }
        __syncthreads();
        compute(c & 1);
        __syncthreads();
    }

    // ---- epilogue ----
#pragma unroll
    for (int mi = 0; mi < 2; mi++)
#pragma unroll
        for (int ni = 0; ni < NI; ni++)
#pragma unroll
            for (int hh = 0; hh < 2; hh++) {
                const int r   = m0 + wr * 32 + mi * 16 + g + hh * 8;
                const int col = n0 + wc * WN + ni * 8 + tg * 2;
                float vx = acc[mi][ni][hh * 2], vy = acc[mi][ni][hh * 2 + 1];
                if (EPI <= 2 && bias) {
                    float2 bb = *(const float2*)(bias + col);
                    vx += bb.x; vy += bb.y;
                }
                if (EPI == 1) {
                    vx = 0.5f * vx * (1.f + erff(vx * 0.70710678118654752f));
                    vy = 0.5f * vy * (1.f + erff(vy * 0.70710678118654752f));
                }
                if (EPI == 2) {
                    float2 rr = *(const float2*)(resp + (size_t)r * ldc + col);
                    vx += rr.x; vy += rr.y;
                }
                if (EPI == 3) {
                    const unsigned char* Mp = mask + (size_t)zb * N + col;
                    float2 ee = *(const float2*)(edge + ((size_t)zb * M + r) * N + col);
                    vx = (Mp[0] ? -FLT_MAX : vx * alpha) + ee.x;
                    vy = (Mp[1] ? -FLT_MAX : vy * alpha) + ee.y;
                }
                if (RND) { vx = to_tf32(vx); vy = to_tf32(vy); }
                *(float2*)(C + (size_t)r * ldc + col) = make_float2(vx, vy);
            }
}

// ---------------- transposes (tf32 pre-round) --------------------------------
__global__ void transpose_s(const float* __restrict__ in, float* __restrict__ out,
                            int R, int Ccols)
{
    const size_t zo = (size_t)blockIdx.z * R * Ccols;
    in += zo; out += zo;
    __shared__ float t[32][33];
    const int c0 = blockIdx.x * 32, r0 = blockIdx.y * 32;
    const int x = threadIdx.x, y = threadIdx.y;
#pragma unroll
    for (int i = 0; i < 32; i += 8)
        t[y + i][x] = to_tf32(in[(size_t)(r0 + y + i) * Ccols + c0 + x]);
    __syncthreads();
#pragma unroll
    for (int i = 0; i < 32; i += 8) out[(size_t)(c0 + y + i) * R + r0 + x] = t[x][y + i];
}

__global__ void vtrans_k(const float* __restrict__ v, float* __restrict__ vT)
{
    const int z = blockIdx.z, b = z >> 3, h = z & 7;
    const float* in = v + (size_t)b * SS * EE + h * DD;
    float* out = vT + (size_t)z * DD * SS;
    __shared__ float t[32][33];
    const int d0 = blockIdx.x * 32, s0 = blockIdx.y * 32;
    const int x = threadIdx.x, y = threadIdx.y;
#pragma unroll
    for (int i = 0; i < 32; i += 8)
        t[y + i][x] = in[(size_t)(s0 + y + i) * EE + d0 + x];   // already rounded by EPI0
    __syncthreads();
#pragma unroll
    for (int i = 0; i < 32; i += 8) out[(size_t)(d0 + y + i) * SS + s0 + x] = t[x][y + i];
}

// ---------------- layernorm (tf32 pre-rounded output) ------------------------
__global__ __launch_bounds__(128)
void ln_k(const float* __restrict__ x, const float* __restrict__ g,
          const float* __restrict__ b, float* __restrict__ o)
{
    const size_t row = blockIdx.x;
    const int tid = threadIdx.x;
    __shared__ float sma[4], smb[4];

    float4 v = ((const float4*)(x + row * EE))[tid];
    float s = v.x + v.y + v.z + v.w;
#pragma unroll
    for (int off = 16; off > 0; off >>= 1) s += __shfl_xor_sync(0xffffffffu, s, off);
    if ((tid & 31) == 0) sma[tid >> 5] = s;
    __syncthreads();
    const float mu = (sma[0] + sma[1] + sma[2] + sma[3]) * (1.f / EE);

    float4 d = make_float4(v.x - mu, v.y - mu, v.z - mu, v.w - mu);
    float s2 = d.x*d.x + d.y*d.y + d.z*d.z + d.w*d.w;
#pragma unroll
    for (int off = 16; off > 0; off >>= 1) s2 += __shfl_xor_sync(0xffffffffu, s2, off);
    if ((tid & 31) == 0) smb[tid >> 5] = s2;
    __syncthreads();
    const float var = (smb[0] + smb[1] + smb[2] + smb[3]) * (1.f / EE);
    const float rstd = rsqrtf(var + 1e-5f);

    float4 gg = ((const float4*)g)[tid];
    float4 bb = ((const float4*)b)[tid];
    float4 out = make_float4(to_tf32(d.x*rstd*gg.x + bb.x), to_tf32(d.y*rstd*gg.y + bb.y),
                             to_tf32(d.z*rstd*gg.z + bb.z), to_tf32(d.w*rstd*gg.w + bb.w));
    ((float4*)(o + row * EE))[tid] = out;
}

// ---------------- softmax (tf32 pre-rounded output) ---------------------------
__global__ __launch_bounds__(256)
void softmax_k(float* __restrict__ s)
{
    float* p = s + (size_t)blockIdx.x * SS;
    const int tid = threadIdx.x;
    __shared__ float sma[8], smb[8];

    float4 v = ((float4*)p)[tid];
    float m = fmaxf(fmaxf(v.x, v.y), fmaxf(v.z, v.w));
#pragma unroll
    for (int off = 16; off > 0; off >>= 1) m = fmaxf(m, __shfl_xor_sync(0xffffffffu, m, off));
    if ((tid & 31) == 0) sma[tid >> 5] = m;
    __syncthreads();
    m = sma[0];
#pragma unroll
    for (int i = 1; i < 8; i++) m = fmaxf(m, sma[i]);

    v.x = expf(v.x - m); v.y = expf(v.y - m);
    v.z = expf(v.z - m); v.w = expf(v.w - m);
    float su = v.x + v.y + v.z + v.w;
#pragma unroll
    for (int off = 16; off > 0; off >>= 1) su += __shfl_xor_sync(0xffffffffu, su, off);
    if ((tid & 31) == 0) smb[tid >> 5] = su;
    __syncthreads();
    float tot = smb[0];
#pragma unroll
    for (int i = 1; i < 8; i++) tot += smb[i];
    const float inv = 1.f / tot;
    v.x = to_tf32(v.x * inv); v.y = to_tf32(v.y * inv);
    v.z = to_tf32(v.z * inv); v.w = to_tf32(v.w * inv);
    ((float4*)p)[tid] = v;
}

// ---------------- host orchestration ----------------------------------------
extern "C" void kernel_launch(void* const* d_in, const int* in_sizes, int n_in,
                              void* d_out, int out_size)
{
    const float* src  = (const float*)d_in[0];
    const float* edge = (const float*)d_in[1];
    const unsigned char* mask = (const unsigned char*)d_in[2];
    const float* Wq = (const float*)d_in[3];
    const float* bq = (const float*)d_in[4];
    const float* Wk = (const float*)d_in[5];
    const float* bk = (const float*)d_in[6];
    const float* Wv = (const float*)d_in[7];
    const float* bvv = (const float*)d_in[8];
    const float* Wo = (const float*)d_in[9];
    const float* bo = (const float*)d_in[10];
    const float* ln1g = (const float*)d_in[11];
    const float* ln1b = (const float*)d_in[12];
    const float* ln2g = (const float*)d_in[13];
    const float* ln2b = (const float*)d_in[14];
    const float* W1 = (const float*)d_in[15];
    const float* b1 = (const float*)d_in[16];
    const float* W2 = (const float*)d_in[17];
    const float* b2 = (const float*)d_in[18];

    float *x, *h, *q, *kk, *vv, *vT, *attn, *sc, *ffn;
    float *wqT, *wkT, *wvT, *woT, *w1T, *w2T;
    cudaGetSymbolAddress((void**)&x,    g_x);
    cudaGetSymbolAddress((void**)&h,    g_h);
    cudaGetSymbolAddress((void**)&q,    g_q);
    cudaGetSymbolAddress((void**)&kk,   g_k);
    cudaGetSymbolAddress((void**)&vv,   g_v);
    cudaGetSymbolAddress((void**)&vT,   g_vT);
    cudaGetSymbolAddress((void**)&attn, g_attn);
    cudaGetSymbolAddress((void**)&sc,   g_sc);
    cudaGetSymbolAddress((void**)&ffn,  g_ffn);
    cudaGetSymbolAddress((void**)&wqT,  g_wqT);
    cudaGetSymbolAddress((void**)&wkT,  g_wkT);
    cudaGetSymbolAddress((void**)&wvT,  g_wvT);
    cudaGetSymbolAddress((void**)&woT,  g_woT);
    cudaGetSymbolAddress((void**)&w1T,  g_w1T);
    cudaGetSymbolAddress((void**)&w2T,  g_w2T);

    // dynamic smem: (2*128*36 + 2*BN*36) * 4 bytes
    const int SM128 = (2 * 128 * 36 + 2 * 128 * 36) * 4;  // 73728
    const int SM64  = (2 * 128 * 36 + 2 * 64  * 36) * 4;  // 55296
    cudaFuncSetAttribute(mma_gemm<0,128>, cudaFuncAttributeMaxDynamicSharedMemorySize, SM128);
    cudaFuncSetAttribute(mma_gemm<1,128>, cudaFuncAttributeMaxDynamicSharedMemorySize, SM128);
    cudaFuncSetAttribute(mma_gemm<2,128>, cudaFuncAttributeMaxDynamicSharedMemorySize, SM128);
    cudaFuncSetAttribute(mma_gemm<3,128>, cudaFuncAttributeMaxDynamicSharedMemorySize, SM128);
    cudaFuncSetAttribute(mma_gemm<0,64>,  cudaFuncAttributeMaxDynamicSharedMemorySize, SM64);

    cudaMemcpyAsync(x, src, sizeof(float) * (size_t)MTOT * EE, cudaMemcpyDeviceToDevice);

    // Pre-transpose (and tf32-round) all weights, batched over layers
    dim3 tb(32, 8);
    transpose_s<<<dim3(EE/32,  EE/32,  LLAYERS), tb>>>(Wq, wqT, EE, EE);
    transpose_s<<<dim3(EE/32,  EE/32,  LLAYERS), tb>>>(Wk, wkT, EE, EE);
    transpose_s<<<dim3(EE/32,  EE/32,  LLAYERS), tb>>>(Wv, wvT, EE, EE);
    transpose_s<<<dim3(EE/32,  EE/32,  LLAYERS), tb>>>(Wo, woT, EE, EE);
    transpose_s<<<dim3(FFD/32, EE/32,  LLAYERS), tb>>>(W1, w1T, EE, FFD);
    transpose_s<<<dim3(EE/32,  FFD/32, LLAYERS), tb>>>(W2, w2T, FFD, EE);

    const long long sQ0 = (long long)SS * EE;   // per-batch stride in q/k/v/attn
    const long long sQ1 = DD;                   // per-head stride
    const long long sS0 = (long long)HH * SS * SS;
    const long long sS1 = (long long)SS * SS;
    const long long sV0 = (long long)HH * DD * SS;
    const long long sV1 = (long long)DD * SS;

    for (int l = 0; l < LLAYERS; ++l) {
        const float* bwq = wqT + (size_t)l * EE * EE;
        const float* bwk = wkT + (size_t)l * EE * EE;
        const float* bwv = wvT + (size_t)l * EE * EE;
        const float* bwo = woT + (size_t)l * EE * EE;
        const float* bw1 = w1T + (size_t)l * FFD * EE;
        const float* bw2 = w2T + (size_t)l * EE * FFD;

        ln_k<<<MTOT, 128>>>(x, ln1g + l * EE, ln1b + l * EE, h);

        dim3 gP(EE / 128, MTOT / 128, 1);
        mma_gemm<0,128><<<gP, 256, SM128>>>(h, EE,0,0, bwq, EE,0,0, q,  EE,0,0,
            bq + l*EE, nullptr, MTOT, EE, EE, 1.f, 1, nullptr, nullptr);
        mma_gemm<0,128><<<gP, 256, SM128>>>(h, EE,0,0, bwk, EE,0,0, kk, EE,0,0,
            bk + l*EE, nullptr, MTOT, EE, EE, 1.f, 1, nullptr, nullptr);
        mma_gemm<0,128><<<gP, 256, SM128>>>(h, EE,0,0, bwv, EE,0,0, vv, EE,0,0,
            bvv + l*EE, nullptr, MTOT, EE, EE, 1.f, 1, nullptr, nullptr);

        vtrans_k<<<dim3(DD/32, SS/32, BB*HH), tb>>>(vv, vT);

        // scores = scale*Q@K^T (+mask, +edge)
        dim3 gS(SS / 128, SS / 128, BB * HH);
        mma_gemm<3,128><<<gS, 256, SM128>>>(q, EE, sQ0, sQ1, kk, EE, sQ0, sQ1,
            sc, SS, sS0, sS1, nullptr, nullptr, SS, SS, DD, 0.125f, HH, edge, mask);

        softmax_k<<<BB * HH * SS, 256>>>(sc);

        // attn = probs @ V
        dim3 gA(1, SS / 128, BB * HH);
        mma_gemm<0,64><<<gA, 256, SM64>>>(sc, SS, sS0, sS1, vT, SS, sV0, sV1,
            attn, EE, sQ0, sQ1, nullptr, nullptr, SS, DD, SS, 1.f, HH, nullptr, nullptr);

        // x = x + attn @ Wo + bo
        mma_gemm<2,128><<<gP, 256, SM128>>>(attn, EE,0,0, bwo, EE,0,0, x, EE,0,0,
            bo + l*EE, x, MTOT, EE, EE, 1.f, 1, nullptr, nullptr);

        ln_k<<<MTOT, 128>>>(x, ln2g + l * EE, ln2b + l * EE, h);

        // FFN1 + exact GELU
        dim3 gF(FFD / 128, MTOT / 128, 1);
        mma_gemm<1,128><<<gF, 256, SM128>>>(h, EE,0,0, bw1, EE,0,0, ffn, FFD,0,0,
            b1 + l*FFD, nullptr, MTOT, FFD, EE, 1.f, 1, nullptr, nullptr);

        // FFN2 + residual
        mma_gemm<2,128><<<gP, 256, SM128>>>(ffn, FFD,0,0, bw2, FFD,0,0, x, EE,0,0,
            b2 + l*EE, x, MTOT, EE, FFD, 1.f, 1, nullptr, nullptr);
    }

    cudaMemcpyAsync(d_out, x, sizeof(float) * (size_t)MTOT * EE, cudaMemcpyDeviceToDevice);
}

// round 6
// speedup vs baseline: 3.5627x; 1.1308x over previous
#include <cuda_runtime.h>
#include <cstdint>
#include <math.h>
#include <float.h>

// Problem constants
#define BB  8
#define SS  1024
#define EE  512
#define HH  8
#define DD  64
#define FFD 2048
#define LLAYERS 4
#define MTOT (BB*SS)   // 8192 rows

// ---------------- scratch (static device globals; no allocations) -----------
__device__ float g_x   [BB*SS*EE];
__device__ float g_h   [BB*SS*EE];
__device__ float g_q   [BB*SS*EE];
__device__ float g_k   [BB*SS*EE];
__device__ float g_v   [BB*SS*EE];
__device__ float g_vT  [BB*HH*DD*SS];
__device__ float g_attn[BB*SS*EE];
__device__ float g_ffn [BB*SS*FFD];
// transposed weights (B operand is [N,K] row-major = K-major), tf32-pre-rounded
__device__ float g_wqT[LLAYERS*EE*EE];
__device__ float g_wkT[LLAYERS*EE*EE];
__device__ float g_wvT[LLAYERS*EE*EE];
__device__ float g_woT[LLAYERS*EE*EE];
__device__ float g_w1T[LLAYERS*FFD*EE];
__device__ float g_w2T[LLAYERS*EE*FFD];

// ---------------- helpers ---------------------------------------------------
__device__ __forceinline__ uint32_t smem_u32(const void* p) {
    uint32_t a;
    asm("{ .reg .u64 t; cvta.to.shared.u64 t, %1; cvt.u32.u64 %0, t; }" : "=r"(a) : "l"(p));
    return a;
}
__device__ __forceinline__ float to_tf32(float x) {
    float r; asm("cvt.rna.tf32.f32 %0, %1;" : "=f"(r) : "f"(x)); return r;
}
#define CP_ASYNC16(dst, src) \
    asm volatile("cp.async.ca.shared.global [%0], [%1], 16;" :: "r"(dst), "l"(src))
#define CP_COMMIT() asm volatile("cp.async.commit_group;" ::: "memory")
#define CP_WAIT1()  asm volatile("cp.async.wait_group 1;" ::: "memory")
#define CP_WAIT0()  asm volatile("cp.async.wait_group 0;" ::: "memory")
// tf32-as-b16 ldmatrix: thread lane receives float [lane>>2][lane&3] of each 8x4 tile
#define LDSM4(r0, r1, r2, r3, addr) \
    asm volatile("ldmatrix.sync.aligned.m8n8.x4.shared.b16 {%0,%1,%2,%3}, [%4];" \
        : "=r"(r0), "=r"(r1), "=r"(r2), "=r"(r3) : "r"(addr))
#define MMA_TF32(acc, a, b) \
    asm volatile("mma.sync.aligned.m16n8k8.row.col.f32.tf32.tf32.f32 " \
        "{%0,%1,%2,%3}, {%4,%5,%6,%7}, {%8,%9}, {%0,%1,%2,%3};" \
        : "+f"((acc)[0]), "+f"((acc)[1]), "+f"((acc)[2]), "+f"((acc)[3]) \
        : "r"((a)[0]), "r"((a)[1]), "r"((a)[2]), "r"((a)[3]), "r"((b)[0]), "r"((b)[1]))

// ---------------- mma.sync tf32 GEMM (linear layers) -------------------------
// C[M,N] = epi( A[M,K] @ B[N,K]^T ).  BM=128, BN template, BK=32.
// EPI: 0 +bias (round out), 1 gelu(+bias) (round out), 2 +bias+res
template<int EPI, int BN>
__global__ void __launch_bounds__(256)
mma_gemm(const float* __restrict__ A, int lda,
         const float* __restrict__ Bm, int ldb,
         float* __restrict__ C, int ldc,
         const float* __restrict__ bias, const float* __restrict__ res,
         int M, int N, int K)
{
    constexpr int BM = 128, PAD = 36;
    constexpr int WN = BN / 2, NI = WN / 8;
    constexpr bool RND = (EPI == 0 || EPI == 1);

    extern __shared__ float sm[];
    float* Asm = sm;
    float* Bsm = sm + 2 * BM * PAD;
    const uint32_t sbA = smem_u32(Asm), sbB = smem_u32(Bsm);

    const int tid = threadIdx.x, warp = tid >> 5, lane = tid & 31;
    const int g = lane >> 2, tg = lane & 3;
    const int wr = warp & 3, wc = warp >> 2;
    const int m0 = blockIdx.y * BM, n0 = blockIdx.x * BN;

    const int arow = wr * 32 + ((lane >> 3) & 1) * 8 + (lane & 7);
    const int acol = ((lane >> 4) & 1) * 4;
    const int brow = wc * WN + ((lane >> 4) & 1) * 8 + (lane & 7);
    const int bcol = ((lane >> 3) & 1) * 4;

    float acc[2][NI][4];
#pragma unroll
    for (int mi = 0; mi < 2; mi++)
#pragma unroll
        for (int ni = 0; ni < NI; ni++)
#pragma unroll
            for (int j = 0; j < 4; j++) acc[mi][ni][j] = 0.f;

    auto load_chunk = [&](int c, int buf) {
        const float* Ab = A + (size_t)m0 * lda + c * 32;
#pragma unroll
        for (int i = 0; i < 4; i++) {
            int e = i * 256 + tid, row = e >> 3, c4 = e & 7;
            CP_ASYNC16(sbA + (uint32_t)(((buf * BM + row) * PAD + c4 * 4) * 4),
                       Ab + (size_t)row * lda + c4 * 4);
        }
        const float* Bb = Bm + (size_t)n0 * ldb + c * 32;
#pragma unroll
        for (int i = 0; i < BN / 32; i++) {
            int e = i * 256 + tid, row = e >> 3, c4 = e & 7;
            CP_ASYNC16(sbB + (uint32_t)(((buf * BN + row) * PAD + c4 * 4) * 4),
                       Bb + (size_t)row * ldb + c4 * 4);
        }
        CP_COMMIT();
    };

    auto compute = [&](int buf) {
        const uint32_t baA = sbA + (uint32_t)(buf * BM * PAD * 4);
        const uint32_t baB = sbB + (uint32_t)(buf * BN * PAD * 4);
#pragma unroll
        for (int ks = 0; ks < 4; ks++) {
            const int k0 = ks * 8;
            uint32_t af[2][4];
#pragma unroll
            for (int mi = 0; mi < 2; mi++)
                LDSM4(af[mi][0], af[mi][1], af[mi][2], af[mi][3],
                      baA + (uint32_t)((((arow + mi * 16) * PAD) + k0 + acol) * 4));
            uint32_t bf[NI][2];
#pragma unroll
            for (int p = 0; p < NI / 2; p++) {
                uint32_t r0, r1, r2, r3;
                LDSM4(r0, r1, r2, r3,
                      baB + (uint32_t)((((brow + p * 16) * PAD) + k0 + bcol) * 4));
                bf[2*p][0] = r0; bf[2*p][1] = r1;
                bf[2*p+1][0] = r2; bf[2*p+1][1] = r3;
            }
#pragma unroll
            for (int mi = 0; mi < 2; mi++)
#pragma unroll
                for (int ni = 0; ni < NI; ni++)
                    MMA_TF32(acc[mi][ni], af[mi], bf[ni]);
        }
    };

    const int nch = K >> 5;
    load_chunk(0, 0);
    for (int c = 0; c < nch; ++c) {
        if (c + 1 < nch) { load_chunk(c + 1, (c + 1) & 1); CP_WAIT1(); }
        else             { CP_WAIT0(); }
        __syncthreads();
        compute(c & 1);
        __syncthreads();
    }

#pragma unroll
    for (int mi = 0; mi < 2; mi++)
#pragma unroll
        for (int ni = 0; ni < NI; ni++)
#pragma unroll
            for (int hh = 0; hh < 2; hh++) {
                const int r   = m0 + wr * 32 + mi * 16 + g + hh * 8;
                const int col = n0 + wc * WN + ni * 8 + tg * 2;
                float vx = acc[mi][ni][hh * 2], vy = acc[mi][ni][hh * 2 + 1];
                if (bias) {
                    float2 bb = *(const float2*)(bias + col);
                    vx += bb.x; vy += bb.y;
                }
                if (EPI == 1) {
                    vx = 0.5f * vx * (1.f + erff(vx * 0.70710678118654752f));
                    vy = 0.5f * vy * (1.f + erff(vy * 0.70710678118654752f));
                }
                if (EPI == 2) {
                    float2 rr = *(const float2*)(res + (size_t)r * ldc + col);
                    vx += rr.x; vy += rr.y;
                }
                if (RND) { vx = to_tf32(vx); vy = to_tf32(vy); }
                *(float2*)(C + (size_t)r * ldc + col) = make_float2(vx, vy);
            }
}

// ---------------- fused flash attention --------------------------------------
// One block: 128 q-rows of one (b,h). Streams K/V/edge in 128-col tiles,
// online softmax, O accumulated in registers. Writes attn (tf32-rounded).
#define PQ  68
#define PS  132
__global__ void __launch_bounds__(256)
flash_k(const float* __restrict__ q, const float* __restrict__ kg,
        const float* __restrict__ vt, float* __restrict__ o,
        const float* __restrict__ edge, const unsigned char* __restrict__ mask)
{
    extern __shared__ float sm[];
    float* Qs  = sm;                    // 128*68
    float* Ks  = Qs + 128 * PQ;         // 128*68
    float* Vs  = Ks + 128 * PQ;         // 64*132
    float* Ssm = Vs + 64 * PS;          // 128*132
    float* mrow = Ssm + 128 * PS;       // 128
    float* lrow = mrow + 128;           // 128
    float* rowf = lrow + 128;           // 128

    const int tid = threadIdx.x, warp = tid >> 5, lane = tid & 31;
    const int g = lane >> 2, tg = lane & 3;
    const int wr = warp & 3, wc = warp >> 2;
    const int t0 = blockIdx.x * 128;
    const int bh = blockIdx.y, b = bh >> 3, h = bh & 7;

    const float* Qg = q  + ((size_t)b * SS + t0) * EE + h * DD;
    const float* Kg = kg + (size_t)b * SS * EE + h * DD;
    const float* Vg = vt + (size_t)bh * DD * SS;
    const uint32_t sQ = smem_u32(Qs), sK = smem_u32(Ks);
    const uint32_t sV = smem_u32(Vs), sS = smem_u32(Ssm);

    // load Q tile (128 x 64)
#pragma unroll
    for (int i = 0; i < 8; i++) {
        int e = i * 256 + tid, row = e >> 4, c4 = e & 15;
        CP_ASYNC16(sQ + (uint32_t)((row * PQ + c4 * 4) * 4), Qg + (size_t)row * EE + c4 * 4);
    }
    CP_COMMIT();
    if (tid < 128) { mrow[tid] = -FLT_MAX; lrow[tid] = 0.f; }

    float acco[2][4][4];
#pragma unroll
    for (int mi = 0; mi < 2; mi++)
#pragma unroll
        for (int ni = 0; ni < 4; ni++)
#pragma unroll
            for (int j = 0; j < 4; j++) acco[mi][ni][j] = 0.f;

    const int arow  = wr * 32 + ((lane >> 3) & 1) * 8 + (lane & 7);
    const int acol  = ((lane >> 4) & 1) * 4;
    const int brow8 = ((lane >> 4) & 1) * 8 + (lane & 7);
    const int bcol  = ((lane >> 3) & 1) * 4;

    for (int kt = 0; kt < 8; kt++) {
        const int s0 = kt * 128;
        // load K (128x64) and Vt (64x128)
#pragma unroll
        for (int i = 0; i < 8; i++) {
            int e = i * 256 + tid, row = e >> 4, c4 = e & 15;
            CP_ASYNC16(sK + (uint32_t)((row * PQ + c4 * 4) * 4),
                       Kg + (size_t)(s0 + row) * EE + c4 * 4);
        }
#pragma unroll
        for (int i = 0; i < 8; i++) {
            int e = i * 256 + tid, row = e >> 5, c4 = e & 31;
            CP_ASYNC16(sV + (uint32_t)((row * PS + c4 * 4) * 4),
                       Vg + (size_t)row * SS + s0 + c4 * 4);
        }
        CP_COMMIT(); CP_WAIT0();
        __syncthreads();

        // S = Q @ K^T (128x128), warp tile 32x64
        float accs[2][8][4];
#pragma unroll
        for (int mi = 0; mi < 2; mi++)
#pragma unroll
            for (int ni = 0; ni < 8; ni++)
#pragma unroll
                for (int j = 0; j < 4; j++) accs[mi][ni][j] = 0.f;
#pragma unroll
        for (int ks = 0; ks < 8; ks++) {
            const int k0 = ks * 8;
            uint32_t af[2][4];
#pragma unroll
            for (int mi = 0; mi < 2; mi++)
                LDSM4(af[mi][0], af[mi][1], af[mi][2], af[mi][3],
                      sQ + (uint32_t)(((arow + mi * 16) * PQ + k0 + acol) * 4));
            uint32_t bf[8][2];
#pragma unroll
            for (int p = 0; p < 4; p++) {
                uint32_t r0, r1, r2, r3;
                LDSM4(r0, r1, r2, r3,
                      sK + (uint32_t)(((wc * 64 + brow8 + p * 16) * PQ + k0 + bcol) * 4));
                bf[2*p][0] = r0; bf[2*p][1] = r1;
                bf[2*p+1][0] = r2; bf[2*p+1][1] = r3;
            }
#pragma unroll
            for (int mi = 0; mi < 2; mi++)
#pragma unroll
                for (int ni = 0; ni < 8; ni++)
                    MMA_TF32(accs[mi][ni], af[mi], bf[ni]);
        }

        // scale + mask + edge -> Ssm
#pragma unroll
        for (int mi = 0; mi < 2; mi++)
#pragma unroll
            for (int ni = 0; ni < 8; ni++)
#pragma unroll
                for (int hh = 0; hh < 2; hh++) {
                    const int r  = wr * 32 + mi * 16 + g + hh * 8;
                    const int cc = wc * 64 + ni * 8 + tg * 2;
                    float2 ee = *(const float2*)(edge + ((size_t)b * SS + t0 + r) * SS + s0 + cc);
                    const unsigned char* Mp = mask + (size_t)b * SS + s0 + cc;
                    float vx = (Mp[0] ? -FLT_MAX : accs[mi][ni][hh*2]     * 0.125f) + ee.x;
                    float vy = (Mp[1] ? -FLT_MAX : accs[mi][ni][hh*2 + 1] * 0.125f) + ee.y;
                    Ssm[r * PS + cc]     = vx;
                    Ssm[r * PS + cc + 1] = vy;
                }
        __syncthreads();

        // online softmax: 2 threads per row, 64 cols each
        {
            const int r = tid >> 1, hf = tid & 1;
            float* Sr = Ssm + r * PS + hf * 64;
            float mloc = -FLT_MAX;
#pragma unroll
            for (int j = 0; j < 64; j += 4) {
                float4 v4 = *(float4*)(Sr + j);
                mloc = fmaxf(mloc, fmaxf(fmaxf(v4.x, v4.y), fmaxf(v4.z, v4.w)));
            }
            mloc = fmaxf(mloc, __shfl_xor_sync(0xffffffffu, mloc, 1));
            const float mold = mrow[r];
            const float mnew = fmaxf(mold, mloc);
            const float f = __expf(mold - mnew);
            float sum = 0.f;
#pragma unroll
            for (int j = 0; j < 64; j += 4) {
                float4 v4 = *(float4*)(Sr + j);
                v4.x = __expf(v4.x - mnew); v4.y = __expf(v4.y - mnew);
                v4.z = __expf(v4.z - mnew); v4.w = __expf(v4.w - mnew);
                sum += v4.x + v4.y + v4.z + v4.w;
                v4.x = to_tf32(v4.x); v4.y = to_tf32(v4.y);
                v4.z = to_tf32(v4.z); v4.w = to_tf32(v4.w);
                *(float4*)(Sr + j) = v4;
            }
            sum += __shfl_xor_sync(0xffffffffu, sum, 1);
            if (hf == 0) { mrow[r] = mnew; rowf[r] = f; lrow[r] = lrow[r] * f + sum; }
        }
        __syncthreads();

        // rescale O accumulators
#pragma unroll
        for (int mi = 0; mi < 2; mi++)
#pragma unroll
            for (int hh = 0; hh < 2; hh++) {
                const int r = wr * 32 + mi * 16 + g + hh * 8;
                const float f = rowf[r];
#pragma unroll
                for (int ni = 0; ni < 4; ni++) {
                    acco[mi][ni][hh*2]     *= f;
                    acco[mi][ni][hh*2 + 1] *= f;
                }
            }

        // O += P @ V  (P: 128x128 from Ssm, Vt: 64x128), warp tile 32x32
#pragma unroll
        for (int ks = 0; ks < 16; ks++) {
            const int k0 = ks * 8;
            uint32_t af[2][4];
#pragma unroll
            for (int mi = 0; mi < 2; mi++)
                LDSM4(af[mi][0], af[mi][1], af[mi][2], af[mi][3],
                      sS + (uint32_t)(((arow + mi * 16) * PS + k0 + acol) * 4));
            uint32_t bf[4][2];
#pragma unroll
            for (int p = 0; p < 2; p++) {
                uint32_t r0, r1, r2, r3;
                LDSM4(r0, r1, r2, r3,
                      sV + (uint32_t)(((wc * 32 + brow8 + p * 16) * PS + k0 + bcol) * 4));
                bf[2*p][0] = r0; bf[2*p][1] = r1;
                bf[2*p+1][0] = r2; bf[2*p+1][1] = r3;
            }
#pragma unroll
            for (int mi = 0; mi < 2; mi++)
#pragma unroll
                for (int ni = 0; ni < 4; ni++)
                    MMA_TF32(acco[mi][ni], af[mi], bf[ni]);
        }
        __syncthreads();
    }

    // write O = acc / l (tf32-rounded, feeds Wo GEMM)
#pragma unroll
    for (int mi = 0; mi < 2; mi++)
#pragma unroll
        for (int ni = 0; ni < 4; ni++)
#pragma unroll
            for (int hh = 0; hh < 2; hh++) {
                const int r = wr * 32 + mi * 16 + g + hh * 8;
                const int d = wc * 32 + ni * 8 + tg * 2;
                const float inv = 1.f / lrow[r];
                float2 out = make_float2(to_tf32(acco[mi][ni][hh*2] * inv),
                                         to_tf32(acco[mi][ni][hh*2 + 1] * inv));
                *(float2*)(o + ((size_t)b * SS + t0 + r) * EE + h * DD + d) = out;
            }
}

// ---------------- transposes (tf32 pre-round) --------------------------------
__global__ void transpose_s(const float* __restrict__ in, float* __restrict__ out,
                            int R, int Ccols)
{
    const size_t zo = (size_t)blockIdx.z * R * Ccols;
    in += zo; out += zo;
    __shared__ float t[32][33];
    const int c0 = blockIdx.x * 32, r0 = blockIdx.y * 32;
    const int x = threadIdx.x, y = threadIdx.y;
#pragma unroll
    for (int i = 0; i < 32; i += 8)
        t[y + i][x] = to_tf32(in[(size_t)(r0 + y + i) * Ccols + c0 + x]);
    __syncthreads();
#pragma unroll
    for (int i = 0; i < 32; i += 8) out[(size_t)(c0 + y + i) * R + r0 + x] = t[x][y + i];
}

__global__ void vtrans_k(const float* __restrict__ v, float* __restrict__ vT)
{
    const int z = blockIdx.z, b = z >> 3, h = z & 7;
    const float* in = v + (size_t)b * SS * EE + h * DD;
    float* out = vT + (size_t)z * DD * SS;
    __shared__ float t[32][33];
    const int d0 = blockIdx.x * 32, s0 = blockIdx.y * 32;
    const int x = threadIdx.x, y = threadIdx.y;
#pragma unroll
    for (int i = 0; i < 32; i += 8)
        t[y + i][x] = in[(size_t)(s0 + y + i) * EE + d0 + x];
    __syncthreads();
#pragma unroll
    for (int i = 0; i < 32; i += 8) out[(size_t)(d0 + y + i) * SS + s0 + x] = t[x][y + i];
}

// ---------------- layernorm (tf32 pre-rounded output) ------------------------
__global__ __launch_bounds__(128)
void ln_k(const float* __restrict__ x, const float* __restrict__ g,
          const float* __restrict__ b, float* __restrict__ o)
{
    const size_t row = blockIdx.x;
    const int tid = threadIdx.x;
    __shared__ float sma[4], smb[4];

    float4 v = ((const float4*)(x + row * EE))[tid];
    float s = v.x + v.y + v.z + v.w;
#pragma unroll
    for (int off = 16; off > 0; off >>= 1) s += __shfl_xor_sync(0xffffffffu, s, off);
    if ((tid & 31) == 0) sma[tid >> 5] = s;
    __syncthreads();
    const float mu = (sma[0] + sma[1] + sma[2] + sma[3]) * (1.f / EE);

    float4 d = make_float4(v.x - mu, v.y - mu, v.z - mu, v.w - mu);
    float s2 = d.x*d.x + d.y*d.y + d.z*d.z + d.w*d.w;
#pragma unroll
    for (int off = 16; off > 0; off >>= 1) s2 += __shfl_xor_sync(0xffffffffu, s2, off);
    if ((tid & 31) == 0) smb[tid >> 5] = s2;
    __syncthreads();
    const float var = (smb[0] + smb[1] + smb[2] + smb[3]) * (1.f / EE);
    const float rstd = rsqrtf(var + 1e-5f);

    float4 gg = ((const float4*)g)[tid];
    float4 bb = ((const float4*)b)[tid];
    float4 out = make_float4(to_tf32(d.x*rstd*gg.x + bb.x), to_tf32(d.y*rstd*gg.y + bb.y),
                             to_tf32(d.z*rstd*gg.z + bb.z), to_tf32(d.w*rstd*gg.w + bb.w));
    ((float4*)(o + row * EE))[tid] = out;
}

// ---------------- host orchestration ----------------------------------------
extern "C" void kernel_launch(void* const* d_in, const int* in_sizes, int n_in,
                              void* d_out, int out_size)
{
    const float* src  = (const float*)d_in[0];
    const float* edge = (const float*)d_in[1];
    const unsigned char* mask = (const unsigned char*)d_in[2];
    const float* Wq = (const float*)d_in[3];
    const float* bq = (const float*)d_in[4];
    const float* Wk = (const float*)d_in[5];
    const float* bk = (const float*)d_in[6];
    const float* Wv = (const float*)d_in[7];
    const float* bvv = (const float*)d_in[8];
    const float* Wo = (const float*)d_in[9];
    const float* bo = (const float*)d_in[10];
    const float* ln1g = (const float*)d_in[11];
    const float* ln1b = (const float*)d_in[12];
    const float* ln2g = (const float*)d_in[13];
    const float* ln2b = (const float*)d_in[14];
    const float* W1 = (const float*)d_in[15];
    const float* b1 = (const float*)d_in[16];
    const float* W2 = (const float*)d_in[17];
    const float* b2 = (const float*)d_in[18];

    float *x, *h, *q, *kk, *vv, *vT, *attn, *ffn;
    float *wqT, *wkT, *wvT, *woT, *w1T, *w2T;
    cudaGetSymbolAddress((void**)&x,    g_x);
    cudaGetSymbolAddress((void**)&h,    g_h);
    cudaGetSymbolAddress((void**)&q,    g_q);
    cudaGetSymbolAddress((void**)&kk,   g_k);
    cudaGetSymbolAddress((void**)&vv,   g_v);
    cudaGetSymbolAddress((void**)&vT,   g_vT);
    cudaGetSymbolAddress((void**)&attn, g_attn);
    cudaGetSymbolAddress((void**)&ffn,  g_ffn);
    cudaGetSymbolAddress((void**)&wqT,  g_wqT);
    cudaGetSymbolAddress((void**)&wkT,  g_wkT);
    cudaGetSymbolAddress((void**)&wvT,  g_wvT);
    cudaGetSymbolAddress((void**)&woT,  g_woT);
    cudaGetSymbolAddress((void**)&w1T,  g_w1T);
    cudaGetSymbolAddress((void**)&w2T,  g_w2T);

    const int SM128 = (2 * 128 * 36 + 2 * 128 * 36) * 4;  // 73728
    const int SMFL  = (128*PQ + 128*PQ + 64*PS + 128*PS + 3*128) * 4;  // 172544
    cudaFuncSetAttribute(mma_gemm<0,128>, cudaFuncAttributeMaxDynamicSharedMemorySize, SM128);
    cudaFuncSetAttribute(mma_gemm<1,128>, cudaFuncAttributeMaxDynamicSharedMemorySize, SM128);
    cudaFuncSetAttribute(mma_gemm<2,128>, cudaFuncAttributeMaxDynamicSharedMemorySize, SM128);
    cudaFuncSetAttribute(flash_k, cudaFuncAttributeMaxDynamicSharedMemorySize, SMFL);

    cudaMemcpyAsync(x, src, sizeof(float) * (size_t)MTOT * EE, cudaMemcpyDeviceToDevice);

    // Pre-transpose (and tf32-round) all weights, batched over layers
    dim3 tb(32, 8);
    transpose_s<<<dim3(EE/32,  EE/32,  LLAYERS), tb>>>(Wq, wqT, EE, EE);
    transpose_s<<<dim3(EE/32,  EE/32,  LLAYERS), tb>>>(Wk, wkT, EE, EE);
    transpose_s<<<dim3(EE/32,  EE/32,  LLAYERS), tb>>>(Wv, wvT, EE, EE);
    transpose_s<<<dim3(EE/32,  EE/32,  LLAYERS), tb>>>(Wo, woT, EE, EE);
    transpose_s<<<dim3(FFD/32, EE/32,  LLAYERS), tb>>>(W1, w1T, EE, FFD);
    transpose_s<<<dim3(EE/32,  FFD/32, LLAYERS), tb>>>(W2, w2T, FFD, EE);

    for (int l = 0; l < LLAYERS; ++l) {
        const float* bwq = wqT + (size_t)l * EE * EE;
        const float* bwk = wkT + (size_t)l * EE * EE;
        const float* bwv = wvT + (size_t)l * EE * EE;
        const float* bwo = woT + (size_t)l * EE * EE;
        const float* bw1 = w1T + (size_t)l * FFD * EE;
        const float* bw2 = w2T + (size_t)l * EE * FFD;

        ln_k<<<MTOT, 128>>>(x, ln1g + l * EE, ln1b + l * EE, h);

        dim3 gP(EE / 128, MTOT / 128, 1);
        mma_gemm<0,128><<<gP, 256, SM128>>>(h, EE, bwq, EE, q,  EE, bq + l*EE, nullptr, MTOT, EE, EE);
        mma_gemm<0,128><<<gP, 256, SM128>>>(h, EE, bwk, EE, kk, EE, bk + l*EE, nullptr, MTOT, EE, EE);
        mma_gemm<0,128><<<gP, 256, SM128>>>(h, EE, bwv, EE, vv, EE, bvv + l*EE, nullptr, MTOT, EE, EE);

        vtrans_k<<<dim3(DD/32, SS/32, BB*HH), tb>>>(vv, vT);

        // fused attention: scores + mask + edge + softmax + PV
        flash_k<<<dim3(SS/128, BB*HH), 256, SMFL>>>(q, kk, vT, attn, edge, mask);

        // x = x + attn @ Wo + bo
        mma_gemm<2,128><<<gP, 256, SM128>>>(attn, EE, bwo, EE, x, EE, bo + l*EE, x, MTOT, EE, EE);

        ln_k<<<MTOT, 128>>>(x, ln2g + l * EE, ln2b + l * EE, h);

        // FFN1 + exact GELU
        dim3 gF(FFD / 128, MTOT / 128, 1);
        mma_gemm<1,128><<<gF, 256, SM128>>>(h, EE, bw1, EE, ffn, FFD, b1 + l*FFD, nullptr, MTOT, FFD, EE);

        // FFN2 + residual
        mma_gemm<2,128><<<gP, 256, SM128>>>(ffn, FFD, bw2, FFD, x, EE, b2 + l*EE, x, MTOT, EE, FFD);
    }

    cudaMemcpyAsync(d_out, x, sizeof(float) * (size_t)MTOT * EE, cudaMemcpyDeviceToDevice);
}

// round 7
// speedup vs baseline: 5.4041x; 1.5169x over previous
#include <cuda_runtime.h>
#include <cuda_fp16.h>
#include <cstdint>
#include <math.h>
#include <float.h>

// Problem constants
#define BB  8
#define SS  1024
#define EE  512
#define HH  8
#define DD  64
#define FFD 2048
#define LLAYERS 4
#define MTOT (BB*SS)   // 8192 rows

// ---------------- scratch (static device globals; no allocations) -----------
__device__ float  g_x   [BB*SS*EE];          // residual stream (fp32)
__device__ __half g_h   [BB*SS*EE];
__device__ __half g_q   [BB*SS*EE];
__device__ __half g_k   [BB*SS*EE];
__device__ __half g_v   [BB*SS*EE];
__device__ __half g_vT  [BB*HH*DD*SS];
__device__ __half g_attn[BB*SS*EE];
__device__ __half g_ffn [BB*SS*FFD];
// transposed weights [N,K] K-major, fp16
__device__ __half g_wqT[LLAYERS*EE*EE];
__device__ __half g_wkT[LLAYERS*EE*EE];
__device__ __half g_wvT[LLAYERS*EE*EE];
__device__ __half g_woT[LLAYERS*EE*EE];
__device__ __half g_w1T[LLAYERS*FFD*EE];
__device__ __half g_w2T[LLAYERS*EE*FFD];

// ---------------- helpers ---------------------------------------------------
__device__ __forceinline__ uint32_t smem_u32(const void* p) {
    uint32_t a;
    asm("{ .reg .u64 t; cvta.to.shared.u64 t, %1; cvt.u32.u64 %0, t; }" : "=r"(a) : "l"(p));
    return a;
}
#define CP_ASYNC16(dst, src) \
    asm volatile("cp.async.ca.shared.global [%0], [%1], 16;" :: "r"(dst), "l"(src))
#define CP_COMMIT() asm volatile("cp.async.commit_group;" ::: "memory")
#define CP_WAIT1()  asm volatile("cp.async.wait_group 1;" ::: "memory")
#define CP_WAIT0()  asm volatile("cp.async.wait_group 0;" ::: "memory")
#define LDSM4(r0, r1, r2, r3, addr) \
    asm volatile("ldmatrix.sync.aligned.m8n8.x4.shared.b16 {%0,%1,%2,%3}, [%4];" \
        : "=r"(r0), "=r"(r1), "=r"(r2), "=r"(r3) : "r"(addr))
#define MMA_F16(acc, a, b) \
    asm volatile("mma.sync.aligned.m16n8k16.row.col.f32.f16.f16.f32 " \
        "{%0,%1,%2,%3}, {%4,%5,%6,%7}, {%8,%9}, {%0,%1,%2,%3};" \
        : "+f"((acc)[0]), "+f"((acc)[1]), "+f"((acc)[2]), "+f"((acc)[3]) \
        : "r"((a)[0]), "r"((a)[1]), "r"((a)[2]), "r"((a)[3]), "r"((b)[0]), "r"((b)[1]))

// ---------------- fp16 mma GEMM (linear layers) ------------------------------
// C[M,N] = epi( A[M,K] @ B[N,K]^T ).  BM=128, BN=128, BK=64 halves.
// 256 threads = 8 warps (4x2), warp tile 32x64.
// EPI: 0 +bias -> half out, 1 gelu(+bias) -> half out, 2 +bias+res -> float out
#define PADH 72
template<int EPI>
__global__ void __launch_bounds__(256)
mma_gemm(const __half* __restrict__ A, int lda,
         const __half* __restrict__ Bm, int ldb,
         void* __restrict__ Cv, int ldc,
         const float* __restrict__ bias, const float* __restrict__ res,
         int M, int N, int K)
{
    constexpr int BM = 128, BN = 128, NI = 8;

    extern __shared__ __half smh[];
    __half* Asm = smh;
    __half* Bsm = smh + 2 * BM * PADH;
    const uint32_t sbA = smem_u32(Asm), sbB = smem_u32(Bsm);

    const int tid = threadIdx.x, warp = tid >> 5, lane = tid & 31;
    const int g = lane >> 2, tg = lane & 3;
    const int wr = warp & 3, wc = warp >> 2;
    const int m0 = blockIdx.y * BM, n0 = blockIdx.x * BN;

    // ldmatrix lane address components (halves)
    const int arow = wr * 32 + ((lane >> 3) & 1) * 8 + (lane & 7);
    const int acol = ((lane >> 4) & 1) * 8;
    const int brow = ((lane >> 4) & 1) * 8 + (lane & 7);
    const int bcol = ((lane >> 3) & 1) * 8;

    float acc[2][NI][4];
#pragma unroll
    for (int mi = 0; mi < 2; mi++)
#pragma unroll
        for (int ni = 0; ni < NI; ni++)
#pragma unroll
            for (int j = 0; j < 4; j++) acc[mi][ni][j] = 0.f;

    auto load_chunk = [&](int c, int buf) {
        const __half* Ab = A + (size_t)m0 * lda + c * 64;
#pragma unroll
        for (int i = 0; i < 4; i++) {
            int e = i * 256 + tid, row = e >> 3, c8 = e & 7;
            CP_ASYNC16(sbA + (uint32_t)(((buf * BM + row) * PADH + c8 * 8) * 2),
                       Ab + (size_t)row * lda + c8 * 8);
        }
        const __half* Bb = Bm + (size_t)n0 * ldb + c * 64;
#pragma unroll
        for (int i = 0; i < 4; i++) {
            int e = i * 256 + tid, row = e >> 3, c8 = e & 7;
            CP_ASYNC16(sbB + (uint32_t)(((buf * BN + row) * PADH + c8 * 8) * 2),
                       Bb + (size_t)row * ldb + c8 * 8);
        }
        CP_COMMIT();
    };

    auto compute = [&](int buf) {
        const uint32_t baA = sbA + (uint32_t)(buf * BM * PADH * 2);
        const uint32_t baB = sbB + (uint32_t)(buf * BN * PADH * 2);
#pragma unroll
        for (int ks = 0; ks < 4; ks++) {
            const int k0 = ks * 16;
            uint32_t af[2][4];
#pragma unroll
            for (int mi = 0; mi < 2; mi++)
                LDSM4(af[mi][0], af[mi][1], af[mi][2], af[mi][3],
                      baA + (uint32_t)(((arow + mi * 16) * PADH + k0 + acol) * 2));
            uint32_t bf[NI][2];
#pragma unroll
            for (int p = 0; p < 4; p++) {
                uint32_t r0, r1, r2, r3;
                LDSM4(r0, r1, r2, r3,
                      baB + (uint32_t)(((wc * 64 + brow + p * 16) * PADH + k0 + bcol) * 2));
                bf[2*p][0] = r0; bf[2*p][1] = r1;
                bf[2*p+1][0] = r2; bf[2*p+1][1] = r3;
            }
#pragma unroll
            for (int mi = 0; mi < 2; mi++)
#pragma unroll
                for (int ni = 0; ni < NI; ni++)
                    MMA_F16(acc[mi][ni], af[mi], bf[ni]);
        }
    };

    const int nch = K >> 6;
    load_chunk(0, 0);
    for (int c = 0; c < nch; ++c) {
        if (c + 1 < nch) { load_chunk(c + 1, (c + 1) & 1); CP_WAIT1(); }
        else             { CP_WAIT0(); }
        __syncthreads();
        compute(c & 1);
        __syncthreads();
    }

#pragma unroll
    for (int mi = 0; mi < 2; mi++)
#pragma unroll
        for (int ni = 0; ni < NI; ni++)
#pragma unroll
            for (int hh = 0; hh < 2; hh++) {
                const int r   = m0 + wr * 32 + mi * 16 + g + hh * 8;
                const int col = n0 + wc * 64 + ni * 8 + tg * 2;
                float vx = acc[mi][ni][hh * 2], vy = acc[mi][ni][hh * 2 + 1];
                float2 bb = *(const float2*)(bias + col);
                vx += bb.x; vy += bb.y;
                if (EPI == 1) {
                    vx = 0.5f * vx * (1.f + erff(vx * 0.70710678118654752f));
                    vy = 0.5f * vy * (1.f + erff(vy * 0.70710678118654752f));
                }
                if (EPI == 2) {
                    float2 rr = *(const float2*)(res + (size_t)r * ldc + col);
                    *(float2*)((float*)Cv + (size_t)r * ldc + col) =
                        make_float2(vx + rr.x, vy + rr.y);
                } else {
                    *(__half2*)((__half*)Cv + (size_t)r * ldc + col) =
                        __floats2half2_rn(vx, vy);
                }
            }
}

// ---------------- fused flash attention (fp16 MMA, fp32 softmax) -------------
#define PVH 136   // V/P row stride in halves
#define PSF 132   // S row stride in floats
__global__ void __launch_bounds__(256)
flash_k(const __half* __restrict__ q, const __half* __restrict__ kg,
        const __half* __restrict__ vt, __half* __restrict__ o,
        const float* __restrict__ edge, const unsigned char* __restrict__ mask)
{
    extern __shared__ char smc[];
    __half* Qs  = (__half*)smc;                       // 128*72 h
    __half* Ks  = Qs + 128 * PADH;                    // 128*72 h
    __half* Vs  = Ks + 128 * PADH;                    // 64*136 h
    __half* Ps  = Vs + 64 * PVH;                      // 128*136 h
    float*  Ssm = (float*)(Ps + 128 * PVH);           // 128*132 f
    float*  mrow = Ssm + 128 * PSF;
    float*  lrow = mrow + 128;
    float*  rowf = lrow + 128;

    const int tid = threadIdx.x, warp = tid >> 5, lane = tid & 31;
    const int g = lane >> 2, tg = lane & 3;
    const int wr = warp & 3, wc = warp >> 2;
    const int t0 = blockIdx.x * 128;
    const int bh = blockIdx.y, b = bh >> 3, h = bh & 7;

    const __half* Qg = q  + ((size_t)b * SS + t0) * EE + h * DD;
    const __half* Kg = kg + (size_t)b * SS * EE + h * DD;
    const __half* Vg = vt + (size_t)bh * DD * SS;
    const uint32_t sQ = smem_u32(Qs), sK = smem_u32(Ks);
    const uint32_t sV = smem_u32(Vs), sP = smem_u32(Ps);

    // load Q tile (128 x 64 halves)
#pragma unroll
    for (int i = 0; i < 4; i++) {
        int e = i * 256 + tid, row = e >> 3, c8 = e & 7;
        CP_ASYNC16(sQ + (uint32_t)((row * PADH + c8 * 8) * 2), Qg + (size_t)row * EE + c8 * 8);
    }
    CP_COMMIT();
    if (tid < 128) { mrow[tid] = -FLT_MAX; lrow[tid] = 0.f; }

    float acco[2][4][4];
#pragma unroll
    for (int mi = 0; mi < 2; mi++)
#pragma unroll
        for (int ni = 0; ni < 4; ni++)
#pragma unroll
            for (int j = 0; j < 4; j++) acco[mi][ni][j] = 0.f;

    const int arow = wr * 32 + ((lane >> 3) & 1) * 8 + (lane & 7);
    const int acol = ((lane >> 4) & 1) * 8;
    const int brow = ((lane >> 4) & 1) * 8 + (lane & 7);
    const int bcol = ((lane >> 3) & 1) * 8;

    for (int kt = 0; kt < 8; kt++) {
        const int s0 = kt * 128;
        // K tile (128 x 64 h), V tile (64 x 128 h)
#pragma unroll
        for (int i = 0; i < 4; i++) {
            int e = i * 256 + tid, row = e >> 3, c8 = e & 7;
            CP_ASYNC16(sK + (uint32_t)((row * PADH + c8 * 8) * 2),
                       Kg + (size_t)(s0 + row) * EE + c8 * 8);
        }
#pragma unroll
        for (int i = 0; i < 4; i++) {
            int e = i * 256 + tid, row = e >> 4, c8 = e & 15;
            CP_ASYNC16(sV + (uint32_t)((row * PVH + c8 * 8) * 2),
                       Vg + (size_t)row * SS + s0 + c8 * 8);
        }
        CP_COMMIT(); CP_WAIT0();
        __syncthreads();

        // S = Q @ K^T (128x128), warp tile 32x64, k=64 -> 4 k16 steps
        float accs[2][8][4];
#pragma unroll
        for (int mi = 0; mi < 2; mi++)
#pragma unroll
            for (int ni = 0; ni < 8; ni++)
#pragma unroll
                for (int j = 0; j < 4; j++) accs[mi][ni][j] = 0.f;
#pragma unroll
        for (int ks = 0; ks < 4; ks++) {
            const int k0 = ks * 16;
            uint32_t af[2][4];
#pragma unroll
            for (int mi = 0; mi < 2; mi++)
                LDSM4(af[mi][0], af[mi][1], af[mi][2], af[mi][3],
                      sQ + (uint32_t)(((arow + mi * 16) * PADH + k0 + acol) * 2));
            uint32_t bf[8][2];
#pragma unroll
            for (int p = 0; p < 4; p++) {
                uint32_t r0, r1, r2, r3;
                LDSM4(r0, r1, r2, r3,
                      sK + (uint32_t)(((wc * 64 + brow + p * 16) * PADH + k0 + bcol) * 2));
                bf[2*p][0] = r0; bf[2*p][1] = r1;
                bf[2*p+1][0] = r2; bf[2*p+1][1] = r3;
            }
#pragma unroll
            for (int mi = 0; mi < 2; mi++)
#pragma unroll
                for (int ni = 0; ni < 8; ni++)
                    MMA_F16(accs[mi][ni], af[mi], bf[ni]);
        }

        // scale + mask + edge -> Ssm (fp32)
#pragma unroll
        for (int mi = 0; mi < 2; mi++)
#pragma unroll
            for (int ni = 0; ni < 8; ni++)
#pragma unroll
                for (int hh = 0; hh < 2; hh++) {
                    const int r  = wr * 32 + mi * 16 + g + hh * 8;
                    const int cc = wc * 64 + ni * 8 + tg * 2;
                    float2 ee = *(const float2*)(edge + ((size_t)b * SS + t0 + r) * SS + s0 + cc);
                    const unsigned char* Mp = mask + (size_t)b * SS + s0 + cc;
                    Ssm[r * PSF + cc]     = (Mp[0] ? -FLT_MAX : accs[mi][ni][hh*2]     * 0.125f) + ee.x;
                    Ssm[r * PSF + cc + 1] = (Mp[1] ? -FLT_MAX : accs[mi][ni][hh*2 + 1] * 0.125f) + ee.y;
                }
        __syncthreads();

        // online softmax: 2 threads per row, 64 cols each; write P as fp16
        {
            const int r = tid >> 1, hf = tid & 1;
            const float* Sr = Ssm + r * PSF + hf * 64;
            __half* Pr = Ps + r * PVH + hf * 64;
            float mloc = -FLT_MAX;
#pragma unroll
            for (int j = 0; j < 64; j += 4) {
                float4 v4 = *(const float4*)(Sr + j);
                mloc = fmaxf(mloc, fmaxf(fmaxf(v4.x, v4.y), fmaxf(v4.z, v4.w)));
            }
            mloc = fmaxf(mloc, __shfl_xor_sync(0xffffffffu, mloc, 1));
            const float mold = mrow[r];
            const float mnew = fmaxf(mold, mloc);
            const float f = __expf(mold - mnew);
            float sum = 0.f;
#pragma unroll
            for (int j = 0; j < 64; j += 4) {
                float4 v4 = *(const float4*)(Sr + j);
                v4.x = __expf(v4.x - mnew); v4.y = __expf(v4.y - mnew);
                v4.z = __expf(v4.z - mnew); v4.w = __expf(v4.w - mnew);
                sum += v4.x + v4.y + v4.z + v4.w;
                *(__half2*)(Pr + j)     = __floats2half2_rn(v4.x, v4.y);
                *(__half2*)(Pr + j + 2) = __floats2half2_rn(v4.z, v4.w);
            }
            sum += __shfl_xor_sync(0xffffffffu, sum, 1);
            if (hf == 0) { mrow[r] = mnew; rowf[r] = f; lrow[r] = lrow[r] * f + sum; }
        }
        __syncthreads();

        // rescale O accumulators
#pragma unroll
        for (int mi = 0; mi < 2; mi++)
#pragma unroll
            for (int hh = 0; hh < 2; hh++) {
                const int r = wr * 32 + mi * 16 + g + hh * 8;
                const float f = rowf[r];
#pragma unroll
                for (int ni = 0; ni < 4; ni++) {
                    acco[mi][ni][hh*2]     *= f;
                    acco[mi][ni][hh*2 + 1] *= f;
                }
            }

        // O += P @ V : P(128x128) @ Vt(64n x 128k), warp tile 32x32, 8 k16 steps
#pragma unroll
        for (int ks = 0; ks < 8; ks++) {
            const int k0 = ks * 16;
            uint32_t af[2][4];
#pragma unroll
            for (int mi = 0; mi < 2; mi++)
                LDSM4(af[mi][0], af[mi][1], af[mi][2], af[mi][3],
                      sP + (uint32_t)(((arow + mi * 16) * PVH + k0 + acol) * 2));
            uint32_t bf[4][2];
#pragma unroll
            for (int p = 0; p < 2; p++) {
                uint32_t r0, r1, r2, r3;
                LDSM4(r0, r1, r2, r3,
                      sV + (uint32_t)(((wc * 32 + brow + p * 16) * PVH + k0 + bcol) * 2));
                bf[2*p][0] = r0; bf[2*p][1] = r1;
                bf[2*p+1][0] = r2; bf[2*p+1][1] = r3;
            }
#pragma unroll
            for (int mi = 0; mi < 2; mi++)
#pragma unroll
                for (int ni = 0; ni < 4; ni++)
                    MMA_F16(acco[mi][ni], af[mi], bf[ni]);
        }
        __syncthreads();
    }

    // write O = acc / l  (fp16, feeds Wo GEMM)
#pragma unroll
    for (int mi = 0; mi < 2; mi++)
#pragma unroll
        for (int ni = 0; ni < 4; ni++)
#pragma unroll
            for (int hh = 0; hh < 2; hh++) {
                const int r = wr * 32 + mi * 16 + g + hh * 8;
                const int d = wc * 32 + ni * 8 + tg * 2;
                const float inv = 1.f / lrow[r];
                *(__half2*)(o + ((size_t)b * SS + t0 + r) * EE + h * DD + d) =
                    __floats2half2_rn(acco[mi][ni][hh*2] * inv, acco[mi][ni][hh*2+1] * inv);
            }
}

// ---------------- weight transpose fp32 -> fp16 ------------------------------
__global__ void transpose_s(const float* __restrict__ in, __half* __restrict__ out,
                            int R, int Ccols)
{
    in  += (size_t)blockIdx.z * R * Ccols;
    out += (size_t)blockIdx.z * R * Ccols;
    __shared__ float t[32][33];
    const int c0 = blockIdx.x * 32, r0 = blockIdx.y * 32;
    const int x = threadIdx.x, y = threadIdx.y;
#pragma unroll
    for (int i = 0; i < 32; i += 8)
        t[y + i][x] = in[(size_t)(r0 + y + i) * Ccols + c0 + x];
    __syncthreads();
#pragma unroll
    for (int i = 0; i < 32; i += 8)
        out[(size_t)(c0 + y + i) * R + r0 + x] = __float2half_rn(t[x][y + i]);
}

// ---------------- V transpose (half -> half) ---------------------------------
__global__ void vtrans_k(const __half* __restrict__ v, __half* __restrict__ vT)
{
    const int z = blockIdx.z, b = z >> 3, h = z & 7;
    const __half* in = v + (size_t)b * SS * EE + h * DD;
    __half* out = vT + (size_t)z * DD * SS;
    __shared__ __half t[32][36];
    const int d0 = blockIdx.x * 32, s0 = blockIdx.y * 32;
    const int x = threadIdx.x, y = threadIdx.y;
#pragma unroll
    for (int i = 0; i < 32; i += 8)
        t[y + i][x] = in[(size_t)(s0 + y + i) * EE + d0 + x];
    __syncthreads();
#pragma unroll
    for (int i = 0; i < 32; i += 8)
        out[(size_t)(d0 + y + i) * SS + s0 + x] = t[x][y + i];
}

// ---------------- layernorm (fp32 in -> fp16 out) ----------------------------
__global__ __launch_bounds__(128)
void ln_k(const float* __restrict__ x, const float* __restrict__ g,
          const float* __restrict__ b, __half* __restrict__ o)
{
    const size_t row = blockIdx.x;
    const int tid = threadIdx.x;
    __shared__ float sma[4], smb[4];

    float4 v = ((const float4*)(x + row * EE))[tid];
    float s = v.x + v.y + v.z + v.w;
#pragma unroll
    for (int off = 16; off > 0; off >>= 1) s += __shfl_xor_sync(0xffffffffu, s, off);
    if ((tid & 31) == 0) sma[tid >> 5] = s;
    __syncthreads();
    const float mu = (sma[0] + sma[1] + sma[2] + sma[3]) * (1.f / EE);

    float4 d = make_float4(v.x - mu, v.y - mu, v.z - mu, v.w - mu);
    float s2 = d.x*d.x + d.y*d.y + d.z*d.z + d.w*d.w;
#pragma unroll
    for (int off = 16; off > 0; off >>= 1) s2 += __shfl_xor_sync(0xffffffffu, s2, off);
    if ((tid & 31) == 0) smb[tid >> 5] = s2;
    __syncthreads();
    const float var = (smb[0] + smb[1] + smb[2] + smb[3]) * (1.f / EE);
    const float rstd = rsqrtf(var + 1e-5f);

    float4 gg = ((const float4*)g)[tid];
    float4 bb = ((const float4*)b)[tid];
    __half2* op = (__half2*)(o + row * EE);
    op[tid * 2]     = __floats2half2_rn(d.x*rstd*gg.x + bb.x, d.y*rstd*gg.y + bb.y);
    op[tid * 2 + 1] = __floats2half2_rn(d.z*rstd*gg.z + bb.z, d.w*rstd*gg.w + bb.w);
}

// ---------------- host orchestration ----------------------------------------
extern "C" void kernel_launch(void* const* d_in, const int* in_sizes, int n_in,
                              void* d_out, int out_size)
{
    const float* src  = (const float*)d_in[0];
    const float* edge = (const float*)d_in[1];
    const unsigned char* mask = (const unsigned char*)d_in[2];
    const float* Wq = (const float*)d_in[3];
    const float* bq = (const float*)d_in[4];
    const float* Wk = (const float*)d_in[5];
    const float* bk = (const float*)d_in[6];
    const float* Wv = (const float*)d_in[7];
    const float* bvv = (const float*)d_in[8];
    const float* Wo = (const float*)d_in[9];
    const float* bo = (const float*)d_in[10];
    const float* ln1g = (const float*)d_in[11];
    const float* ln1b = (const float*)d_in[12];
    const float* ln2g = (const float*)d_in[13];
    const float* ln2b = (const float*)d_in[14];
    const float* W1 = (const float*)d_in[15];
    const float* b1 = (const float*)d_in[16];
    const float* W2 = (const float*)d_in[17];
    const float* b2 = (const float*)d_in[18];

    float *x;
    __half *h, *q, *kk, *vv, *vT, *attn, *ffn;
    __half *wqT, *wkT, *wvT, *woT, *w1T, *w2T;
    cudaGetSymbolAddress((void**)&x,    g_x);
    cudaGetSymbolAddress((void**)&h,    g_h);
    cudaGetSymbolAddress((void**)&q,    g_q);
    cudaGetSymbolAddress((void**)&kk,   g_k);
    cudaGetSymbolAddress((void**)&vv,   g_v);
    cudaGetSymbolAddress((void**)&vT,   g_vT);
    cudaGetSymbolAddress((void**)&attn, g_attn);
    cudaGetSymbolAddress((void**)&ffn,  g_ffn);
    cudaGetSymbolAddress((void**)&wqT,  g_wqT);
    cudaGetSymbolAddress((void**)&wkT,  g_wkT);
    cudaGetSymbolAddress((void**)&wvT,  g_wvT);
    cudaGetSymbolAddress((void**)&woT,  g_woT);
    cudaGetSymbolAddress((void**)&w1T,  g_w1T);
    cudaGetSymbolAddress((void**)&w2T,  g_w2T);

    const int SMG  = (2 * 128 * PADH + 2 * 128 * PADH) * 2;   // 73728 B
    const int SMFL = (128*PADH + 128*PADH + 64*PVH + 128*PVH) * 2
                   + (128*PSF + 3*128) * 4;                    // 158208 B
    cudaFuncSetAttribute(mma_gemm<0>, cudaFuncAttributeMaxDynamicSharedMemorySize, SMG);
    cudaFuncSetAttribute(mma_gemm<1>, cudaFuncAttributeMaxDynamicSharedMemorySize, SMG);
    cudaFuncSetAttribute(mma_gemm<2>, cudaFuncAttributeMaxDynamicSharedMemorySize, SMG);
    cudaFuncSetAttribute(flash_k, cudaFuncAttributeMaxDynamicSharedMemorySize, SMFL);

    cudaMemcpyAsync(x, src, sizeof(float) * (size_t)MTOT * EE, cudaMemcpyDeviceToDevice);

    // Pre-transpose + fp16-convert all weights (batched over layers)
    dim3 tb(32, 8);
    transpose_s<<<dim3(EE/32,  EE/32,  LLAYERS), tb>>>(Wq, wqT, EE, EE);
    transpose_s<<<dim3(EE/32,  EE/32,  LLAYERS), tb>>>(Wk, wkT, EE, EE);
    transpose_s<<<dim3(EE/32,  EE/32,  LLAYERS), tb>>>(Wv, wvT, EE, EE);
    transpose_s<<<dim3(EE/32,  EE/32,  LLAYERS), tb>>>(Wo, woT, EE, EE);
    transpose_s<<<dim3(FFD/32, EE/32,  LLAYERS), tb>>>(W1, w1T, EE, FFD);
    transpose_s<<<dim3(EE/32,  FFD/32, LLAYERS), tb>>>(W2, w2T, FFD, EE);

    for (int l = 0; l < LLAYERS; ++l) {
        const __half* bwq = wqT + (size_t)l * EE * EE;
        const __half* bwk = wkT + (size_t)l * EE * EE;
        const __half* bwv = wvT + (size_t)l * EE * EE;
        const __half* bwo = woT + (size_t)l * EE * EE;
        const __half* bw1 = w1T + (size_t)l * FFD * EE;
        const __half* bw2 = w2T + (size_t)l * EE * FFD;

        ln_k<<<MTOT, 128>>>(x, ln1g + l * EE, ln1b + l * EE, h);

        dim3 gP(EE / 128, MTOT / 128, 1);
        mma_gemm<0><<<gP, 256, SMG>>>(h, EE, bwq, EE, q,  EE, bq + l*EE, nullptr, MTOT, EE, EE);
        mma_gemm<0><<<gP, 256, SMG>>>(h, EE, bwk, EE, kk, EE, bk + l*EE, nullptr, MTOT, EE, EE);
        mma_gemm<0><<<gP, 256, SMG>>>(h, EE, bwv, EE, vv, EE, bvv + l*EE, nullptr, MTOT, EE, EE);

        vtrans_k<<<dim3(DD/32, SS/32, BB*HH), tb>>>(vv, vT);

        // fused attention
        flash_k<<<dim3(SS/128, BB*HH), 256, SMFL>>>(q, kk, vT, attn, edge, mask);

        // x = x + attn @ Wo + bo
        mma_gemm<2><<<gP, 256, SMG>>>(attn, EE, bwo, EE, x, EE, bo + l*EE, x, MTOT, EE, EE);

        ln_k<<<MTOT, 128>>>(x, ln2g + l * EE, ln2b + l * EE, h);

        // FFN1 + exact GELU
        dim3 gF(FFD / 128, MTOT / 128, 1);
        mma_gemm<1><<<gF, 256, SMG>>>(h, EE, bw1, EE, ffn, FFD, b1 + l*FFD, nullptr, MTOT, FFD, EE);

        // FFN2 + residual
        mma_gemm<2><<<gP, 256, SMG>>>(ffn, FFD, bw2, FFD, x, EE, b2 + l*EE, x, MTOT, EE, FFD);
    }

    cudaMemcpyAsync(d_out, x, sizeof(float) * (size_t)MTOT * EE, cudaMemcpyDeviceToDevice);
}